// round 14
// baseline (speedup 1.0000x reference)
#include <cuda_runtime.h>
#include <cuda_fp16.h>
#include <math.h>
#include <stdint.h>

// Problem constants
#define B_   4
#define S_   2048
#define D_   1024
#define H_   16
#define DH_  64
#define FF_  4096
#define NTOK (B_ * S_)   // 8192
#define QKS  3072        // packed qkv row stride

// ---------------------------------------------------------------------------
// Scratch buffers
// ---------------------------------------------------------------------------
__device__ float  g_y1[(size_t)NTOK * D_];
__device__ float  g_x1[(size_t)NTOK * D_];
__device__ float  g_bqkv[QKS];
__device__ __half g_xh[(size_t)NTOK * D_];
__device__ __half g_whqkv[(size_t)D_ * QKS];
__device__ __half g_wh[(size_t)9 * 1024 * 1024];    // wm (1M), w1 (4M), w2 (4M)
__device__ __half g_qkvh[(size_t)NTOK * QKS];       // packed q|k|v fp16
__device__ __half g_ctxh[(size_t)NTOK * D_];
__device__ __half g_x1h[(size_t)NTOK * D_];
__device__ __half g_hbh[(size_t)NTOK * FF_];

// ---------------------------------------------------------------------------
// helpers
// ---------------------------------------------------------------------------
__device__ __forceinline__ void mma_f16(float* d, const uint32_t* a, const uint32_t* b) {
    asm volatile(
        "mma.sync.aligned.m16n8k16.row.col.f32.f16.f16.f32 "
        "{%0,%1,%2,%3}, {%4,%5,%6,%7}, {%8,%9}, {%0,%1,%2,%3};"
        : "+f"(d[0]), "+f"(d[1]), "+f"(d[2]), "+f"(d[3])
        : "r"(a[0]), "r"(a[1]), "r"(a[2]), "r"(a[3]), "r"(b[0]), "r"(b[1]));
}

__device__ __forceinline__ uint32_t smem_u32(const void* p) {
    uint32_t a;
    asm("{ .reg .u64 t; cvta.to.shared.u64 t, %1; cvt.u32.u64 %0, t; }" : "=r"(a) : "l"(p));
    return a;
}

__device__ __forceinline__ void cpasync16(uint32_t dst, const void* src) {
    asm volatile("cp.async.cg.shared.global [%0], [%1], 16;" :: "r"(dst), "l"(src) : "memory");
}
__device__ __forceinline__ void cpasync_commit() {
    asm volatile("cp.async.commit_group;" ::: "memory");
}
template <int N>
__device__ __forceinline__ void cpasync_wait() {
    asm volatile("cp.async.wait_group %0;" :: "n"(N) : "memory");
}

__device__ __forceinline__ void ldsm_x4(uint32_t* r, uint32_t addr) {
    asm volatile("ldmatrix.sync.aligned.m8n8.x4.shared.b16 {%0,%1,%2,%3}, [%4];"
                 : "=r"(r[0]), "=r"(r[1]), "=r"(r[2]), "=r"(r[3]) : "r"(addr));
}
__device__ __forceinline__ void ldsm_x4_t(uint32_t* r, uint32_t addr) {
    asm volatile("ldmatrix.sync.aligned.m8n8.x4.trans.shared.b16 {%0,%1,%2,%3}, [%4];"
                 : "=r"(r[0]), "=r"(r[1]), "=r"(r[2]), "=r"(r[3]) : "r"(addr));
}

__device__ __forceinline__ uint32_t h2u(__half2 h) {
    return *reinterpret_cast<uint32_t*>(&h);
}

// ---------------------------------------------------------------------------
// Pre-pass kernels
// ---------------------------------------------------------------------------
__global__ __launch_bounds__(256) void f2h_kernel(
    const float* __restrict__ src, __half* __restrict__ dst)
{
    const int i = (blockIdx.x * 256 + threadIdx.x) * 4;
    float4 v = *(const float4*)(src + i);
    *(__half2*)(dst + i)     = __floats2half2_rn(v.x, v.y);
    *(__half2*)(dst + i + 2) = __floats2half2_rn(v.z, v.w);
}

__global__ __launch_bounds__(256) void packw_kernel(
    const float* __restrict__ wq, const float* __restrict__ wk,
    const float* __restrict__ wv, const float* __restrict__ wm,
    const float* __restrict__ w1, const float* __restrict__ w2,
    __half* __restrict__ whqkv, __half* __restrict__ whm,
    __half* __restrict__ wh1, __half* __restrict__ wh2)
{
    const int bid = blockIdx.x;
    if (bid < 3072) {
        const int y = bid >> 10;
        const int i = ((bid & 1023) * 256 + threadIdx.x) * 4;
        const float* src = (y == 0) ? wq : (y == 1) ? wk : wv;
        float4 v = *(const float4*)(src + i);
        __half* o = whqkv + (size_t)(i >> 10) * QKS + y * 1024 + (i & 1023);
        *(__half2*)o       = __floats2half2_rn(v.x, v.y);
        *(__half2*)(o + 2) = __floats2half2_rn(v.z, v.w);
    } else if (bid < 4096) {
        const int i = ((bid - 3072) * 256 + threadIdx.x) * 4;
        float4 v = *(const float4*)(wm + i);
        *(__half2*)(whm + i)     = __floats2half2_rn(v.x, v.y);
        *(__half2*)(whm + i + 2) = __floats2half2_rn(v.z, v.w);
    } else if (bid < 8192) {
        const int i = ((bid - 4096) * 256 + threadIdx.x) * 4;
        float4 v = *(const float4*)(w1 + i);
        *(__half2*)(wh1 + i)     = __floats2half2_rn(v.x, v.y);
        *(__half2*)(wh1 + i + 2) = __floats2half2_rn(v.z, v.w);
    } else {
        const int i = ((bid - 8192) * 256 + threadIdx.x) * 4;
        float4 v = *(const float4*)(w2 + i);
        *(__half2*)(wh2 + i)     = __floats2half2_rn(v.x, v.y);
        *(__half2*)(wh2 + i + 2) = __floats2half2_rn(v.z, v.w);
    }
}

__global__ __launch_bounds__(1024) void packb_kernel(
    const float* __restrict__ bq, const float* __restrict__ bk,
    const float* __restrict__ bv, float* __restrict__ out)
{
    const int i = blockIdx.x * 1024 + threadIdx.x;
    out[i] = (i < 1024) ? bq[i] : (i < 2048) ? bk[i - 1024] : bv[i - 2048];
}

// ---------------------------------------------------------------------------
// fp16 GEMM: GK=64, 3-stage cp.async + ldmatrix, 2 CTA/SM, one sync/iter.
// A stage [128][64] halfs (128B rows, 8 chunks, swz c^(row&7))
// B stage [64][128] halfs (256B rows, 16 chunks, swz c^(row&7))
// ---------------------------------------------------------------------------
#define GK 64
#define ASTG (128 * 64)
#define BSTG (64 * 128)
#define STGH (ASTG + BSTG)              // 16384 halfs = 32 KB
#define NSTG 3
#define GEMM_SMEM_BYTES (NSTG * STGH * 2)   // 98304

template <int EPI, bool HOUT>
__device__ __forceinline__ void hgemm_body(
    const __half* __restrict__ A, const __half* __restrict__ W,
    const float* __restrict__ bias, const float* __restrict__ res,
    void* __restrict__ Cv, int M, int N, int K)
{
    extern __shared__ __half hsm[];
    const uint32_t sbase = smem_u32(hsm);

    const int tid = threadIdx.x;
    const int lane = tid & 31;
    const int warp = tid >> 5;
    const int wm = warp >> 2;
    const int wn = warp & 3;
    const int bm = blockIdx.y * 128;
    const int bn = blockIdx.x * 128;

    // A fill: row ar (0..127), chunks ac0..ac0+3 (16B each)
    const int ar = tid >> 1;
    const int ac0 = (tid & 1) * 4;
    // B fill: rows bkr+16r (r=0..3), chunk bnc
    const int bkr = tid >> 4;          // 0..15
    const int bnc = tid & 15;          // 0..15

    const __half* Ag = A + (size_t)bm * K;
    const __half* Wg = W + bn;

    // ldmatrix A coords
    uint32_t a_row_off[4];
    int a_row_sw[4];
#pragma unroll
    for (int i = 0; i < 4; i++) {
        const int row = wm * 64 + i * 16 + (lane & 15);
        a_row_off[i] = (uint32_t)(row * 128);
        a_row_sw[i] = row & 7;
    }
    const int a_csel = lane >> 4;
    const int b_krlo = lane & 15;
    const int b_ncsel = wn * 4 + (lane >> 4);

    float acc[4][4][4];
#pragma unroll
    for (int i = 0; i < 4; i++)
#pragma unroll
        for (int j = 0; j < 4; j++)
#pragma unroll
            for (int r = 0; r < 4; r++) acc[i][j][r] = 0.f;

    const int NIT = K / GK;

    auto issue = [&](int s, int k0) {
        const uint32_t ab = sbase + (uint32_t)(s * STGH) * 2;
        const uint32_t bb = ab + ASTG * 2;
#pragma unroll
        for (int c = 0; c < 4; c++) {
            const int ac = ac0 + c;
            cpasync16(ab + (uint32_t)(ar * 128 + ((ac ^ (ar & 7)) << 4)),
                      Ag + (size_t)ar * K + k0 + ac * 8);
        }
#pragma unroll
        for (int r = 0; r < 4; r++) {
            const int row = bkr + 16 * r;
            cpasync16(bb + (uint32_t)(row * 256 + ((bnc ^ (row & 7)) << 4)),
                      Wg + (size_t)(k0 + row) * N + bnc * 8);
        }
        cpasync_commit();
    };

    issue(0, 0);
    issue(1, GK);

    int stage = 0;
    for (int t = 0; t < NIT; t++) {
        if (t + 1 < NIT) cpasync_wait<1>();
        else cpasync_wait<0>();
        __syncthreads();
        if (t + 2 < NIT) {
            int s2 = stage + 2; if (s2 >= NSTG) s2 -= NSTG;
            issue(s2, (t + 2) * GK);
        }

        const uint32_t ab = sbase + (uint32_t)(stage * STGH) * 2;
        const uint32_t bb = ab + ASTG * 2;

#pragma unroll
        for (int ksb = 0; ksb < 4; ksb++) {
            uint32_t av[4][4];
#pragma unroll
            for (int i = 0; i < 4; i++) {
                const int lch = ksb * 2 + a_csel;
                ldsm_x4(av[i], ab + a_row_off[i] + (uint32_t)((lch ^ a_row_sw[i]) << 4));
            }
            uint32_t bf[4][2];
            const int krow = ksb * 16 + b_krlo;
#pragma unroll
            for (int jj = 0; jj < 2; jj++) {
                uint32_t tmp[4];
                const int nch = b_ncsel + jj * 2;
                ldsm_x4_t(tmp, bb + (uint32_t)(krow * 256) + (uint32_t)((nch ^ (krow & 7)) << 4));
                bf[jj * 2][0] = tmp[0]; bf[jj * 2][1] = tmp[1];
                bf[jj * 2 + 1][0] = tmp[2]; bf[jj * 2 + 1][1] = tmp[3];
            }
#pragma unroll
            for (int i = 0; i < 4; i++)
#pragma unroll
                for (int j = 0; j < 4; j++)
                    mma_f16(acc[i][j], av[i], bf[j]);
        }
        if (++stage == NSTG) stage = 0;
    }

#pragma unroll
    for (int i = 0; i < 4; i++) {
        const int r0 = bm + wm * 64 + i * 16 + (lane >> 2);
#pragma unroll
        for (int j = 0; j < 4; j++) {
            const int col = bn + wn * 32 + j * 8 + (lane & 3) * 2;
            float2 bi = *(const float2*)(bias + col);
            float o00 = acc[i][j][0] + bi.x;
            float o01 = acc[i][j][1] + bi.y;
            float o10 = acc[i][j][2] + bi.x;
            float o11 = acc[i][j][3] + bi.y;
            if (EPI == 1) {
                o00 = fmaxf(o00, 0.f); o01 = fmaxf(o01, 0.f);
                o10 = fmaxf(o10, 0.f); o11 = fmaxf(o11, 0.f);
            }
            if (EPI == 2) {
                float2 r0v = *(const float2*)(res + (size_t)r0 * N + col);
                float2 r1v = *(const float2*)(res + (size_t)(r0 + 8) * N + col);
                o00 += r0v.x; o01 += r0v.y;
                o10 += r1v.x; o11 += r1v.y;
            }
            if (HOUT) {
                __half* Ch = (__half*)Cv;
                *(__half2*)(Ch + (size_t)r0 * N + col) = __floats2half2_rn(o00, o01);
                *(__half2*)(Ch + (size_t)(r0 + 8) * N + col) = __floats2half2_rn(o10, o11);
            } else {
                float* Cf = (float*)Cv;
                *(float2*)(Cf + (size_t)r0 * N + col) = make_float2(o00, o01);
                *(float2*)(Cf + (size_t)(r0 + 8) * N + col) = make_float2(o10, o11);
            }
        }
    }
}

template <int EPI, bool HOUT>
__global__ __launch_bounds__(256, 2) void hgemm_kernel(
    const __half* __restrict__ A, const __half* __restrict__ W,
    const float* __restrict__ bias, const float* __restrict__ res,
    void* __restrict__ C, int M, int N, int K)
{
    hgemm_body<EPI, HOUT>(A, W, bias, res, C, M, N, K);
}

// ---------------------------------------------------------------------------
// fp16 flash attention (round-13 validated, unchanged)
// ---------------------------------------------------------------------------
#define FBK 64
#define KROW 72
#define KBUF (64 * KROW)
#define NSTAGE 3
#define FLASH_SMEM_BYTES (NSTAGE * 2 * KBUF * 2)

__global__ __launch_bounds__(256, 2) void flash_fp16_kernel(
    const __half* __restrict__ qkv, const unsigned char* __restrict__ mask,
    __half* __restrict__ ctxh)
{
    extern __shared__ __half fh[];
    const uint32_t ks_u = smem_u32(fh);
    const uint32_t vs_u = ks_u + NSTAGE * KBUF * 2;

    const int tid = threadIdx.x;
    const int lane = tid & 31;
    const int warp = tid >> 5;
    const int bh = blockIdx.y;
    const int b = bh >> 4;
    const int h = bh & 15;
    const int q0 = blockIdx.x * 128;
    const int hoff = h * DH_;
    const unsigned char* mrow = mask + (size_t)b * S_;

    const int r0 = lane >> 2;
    const int c0 = lane & 3;
    const int lrow = lane & 15;
    const int lhi = lane >> 4;

    uint32_t qf[4][4];
    {
        const size_t rowa = (size_t)(b * S_ + q0 + warp * 16 + r0) * QKS + hoff;
#pragma unroll
        for (int ks = 0; ks < 4; ks++) {
            const int c = ks * 16 + 2 * c0;
            qf[ks][0] = *(const uint32_t*)(qkv + rowa + c);
            qf[ks][1] = *(const uint32_t*)(qkv + rowa + (size_t)8 * QKS + c);
            qf[ks][2] = *(const uint32_t*)(qkv + rowa + c + 8);
            qf[ks][3] = *(const uint32_t*)(qkv + rowa + (size_t)8 * QKS + c + 8);
        }
    }

    float oa[8][4];
    float mx0 = -1e30f, mx1 = -1e30f, l0 = 0.f, l1 = 0.f;
#pragma unroll
    for (int j = 0; j < 8; j++)
#pragma unroll
        for (int r = 0; r < 4; r++) oa[j][r] = 0.f;

    const int id0 = tid, id1 = tid + 256;
    const int krow0 = id0 >> 3, kch0 = id0 & 7;
    const int krow1 = id1 >> 3, kch1 = id1 & 7;

    const __half* kbase = qkv + (size_t)b * S_ * QKS + 1024 + hoff;
    const __half* vbase = qkv + (size_t)b * S_ * QKS + 2048 + hoff;

    const int NT = S_ / FBK;

    auto issue = [&](int st, int kt) {
        const uint32_t kdst = ks_u + (uint32_t)(st * KBUF) * 2;
        const uint32_t vdst = vs_u + (uint32_t)(st * KBUF) * 2;
        cpasync16(kdst + (uint32_t)(krow0 * KROW) * 2 + kch0 * 16,
                  kbase + (size_t)(kt + krow0) * QKS + kch0 * 8);
        cpasync16(kdst + (uint32_t)(krow1 * KROW) * 2 + kch1 * 16,
                  kbase + (size_t)(kt + krow1) * QKS + kch1 * 8);
        cpasync16(vdst + (uint32_t)(krow0 * KROW) * 2 + kch0 * 16,
                  vbase + (size_t)(kt + krow0) * QKS + kch0 * 8);
        cpasync16(vdst + (uint32_t)(krow1 * KROW) * 2 + kch1 * 16,
                  vbase + (size_t)(kt + krow1) * QKS + kch1 * 8);
        cpasync_commit();
    };

    issue(0, 0);
    issue(1, FBK);

    for (int t = 0; t < NT; t++) {
        const int kt = t * FBK;
        if (t + 1 < NT) cpasync_wait<1>();
        else cpasync_wait<0>();
        __syncthreads();
        if (t + 2 < NT) issue((t + 2) % NSTAGE, kt + 2 * FBK);

        const uint32_t kc_u = ks_u + (uint32_t)((t % NSTAGE) * KBUF) * 2;
        const uint32_t vc_u = vs_u + (uint32_t)((t % NSTAGE) * KBUF) * 2;

        float sa[8][4];
#pragma unroll
        for (int j = 0; j < 8; j++)
#pragma unroll
            for (int r = 0; r < 4; r++) sa[j][r] = 0.f;

#pragma unroll
        for (int ks = 0; ks < 4; ks++) {
#pragma unroll
            for (int jp = 0; jp < 4; jp++) {
                uint32_t kv4[4];
                ldsm_x4(kv4, kc_u + (uint32_t)(((jp * 16 + lrow) * KROW + ks * 16 + lhi * 8) * 2));
                uint32_t b0[2] = {kv4[0], kv4[2]};
                uint32_t b1[2] = {kv4[1], kv4[3]};
                mma_f16(sa[2 * jp], qf[ks], b0);
                mma_f16(sa[2 * jp + 1], qf[ks], b1);
            }
        }

        float rm0 = -1e30f, rm1 = -1e30f;
#pragma unroll
        for (int j = 0; j < 8; j++) {
            const int col = kt + j * 8 + 2 * c0;
            const bool m0 = mrow[col] != 0;
            const bool m1 = mrow[col + 1] != 0;
            sa[j][0] = m0 ? -1e9f : sa[j][0] * 0.125f;
            sa[j][1] = m1 ? -1e9f : sa[j][1] * 0.125f;
            sa[j][2] = m0 ? -1e9f : sa[j][2] * 0.125f;
            sa[j][3] = m1 ? -1e9f : sa[j][3] * 0.125f;
            rm0 = fmaxf(rm0, fmaxf(sa[j][0], sa[j][1]));
            rm1 = fmaxf(rm1, fmaxf(sa[j][2], sa[j][3]));
        }
        rm0 = fmaxf(rm0, __shfl_xor_sync(0xffffffffu, rm0, 1));
        rm0 = fmaxf(rm0, __shfl_xor_sync(0xffffffffu, rm0, 2));
        rm1 = fmaxf(rm1, __shfl_xor_sync(0xffffffffu, rm1, 1));
        rm1 = fmaxf(rm1, __shfl_xor_sync(0xffffffffu, rm1, 2));

        const float mn0 = fmaxf(mx0, rm0);
        const float mn1 = fmaxf(mx1, rm1);
        const float corr0 = __expf(mx0 - mn0);
        const float corr1 = __expf(mx1 - mn1);
        mx0 = mn0; mx1 = mn1;

        float rs0 = 0.f, rs1 = 0.f;
#pragma unroll
        for (int j = 0; j < 8; j++) {
            sa[j][0] = __expf(sa[j][0] - mn0);
            sa[j][1] = __expf(sa[j][1] - mn0);
            sa[j][2] = __expf(sa[j][2] - mn1);
            sa[j][3] = __expf(sa[j][3] - mn1);
            rs0 += sa[j][0] + sa[j][1];
            rs1 += sa[j][2] + sa[j][3];
            oa[j][0] *= corr0; oa[j][1] *= corr0;
            oa[j][2] *= corr1; oa[j][3] *= corr1;
        }
        rs0 += __shfl_xor_sync(0xffffffffu, rs0, 1);
        rs0 += __shfl_xor_sync(0xffffffffu, rs0, 2);
        rs1 += __shfl_xor_sync(0xffffffffu, rs1, 1);
        rs1 += __shfl_xor_sync(0xffffffffu, rs1, 2);
        l0 = l0 * corr0 + rs0;
        l1 = l1 * corr1 + rs1;

#pragma unroll
        for (int ks = 0; ks < 4; ks++) {
            uint32_t pf[4];
            pf[0] = h2u(__floats2half2_rn(sa[2 * ks][0], sa[2 * ks][1]));
            pf[1] = h2u(__floats2half2_rn(sa[2 * ks][2], sa[2 * ks][3]));
            pf[2] = h2u(__floats2half2_rn(sa[2 * ks + 1][0], sa[2 * ks + 1][1]));
            pf[3] = h2u(__floats2half2_rn(sa[2 * ks + 1][2], sa[2 * ks + 1][3]));
#pragma unroll
            for (int q = 0; q < 4; q++) {
                uint32_t t4[4];
                ldsm_x4_t(t4, vc_u + (uint32_t)(((ks * 16 + lrow) * KROW + (2 * q + lhi) * 8) * 2));
                mma_f16(oa[2 * q], pf, t4);
                mma_f16(oa[2 * q + 1], pf, t4 + 2);
            }
        }
    }

    const float inv0 = 1.f / l0;
    const float inv1 = 1.f / l1;
    const int row0 = q0 + warp * 16 + r0;
    const size_t obase = (size_t)b * S_ * D_ + hoff;
#pragma unroll
    for (int j = 0; j < 8; j++) {
        const int col = j * 8 + 2 * c0;
        *(__half2*)(ctxh + obase + (size_t)row0 * D_ + col) =
            __floats2half2_rn(oa[j][0] * inv0, oa[j][1] * inv0);
        *(__half2*)(ctxh + obase + (size_t)(row0 + 8) * D_ + col) =
            __floats2half2_rn(oa[j][2] * inv1, oa[j][3] * inv1);
    }
}

// ---------------------------------------------------------------------------
// LayerNorm
// ---------------------------------------------------------------------------
__global__ __launch_bounds__(256) void ln_kernel(
    const float* __restrict__ in, const float* __restrict__ g,
    const float* __restrict__ be, float* __restrict__ out,
    __half* __restrict__ outh)
{
    __shared__ float sred[8], ssred[8];
    __shared__ float muSh, rsSh;

    const int row = blockIdx.x;
    const int tid = threadIdx.x;
    const int lane = tid & 31;
    const int wid = tid >> 5;

    const float* p = in + (size_t)row * D_;
    float4 x = *(const float4*)(p + tid * 4);
    float s = x.x + x.y + x.z + x.w;
    float ss = x.x * x.x + x.y * x.y + x.z * x.z + x.w * x.w;

#pragma unroll
    for (int off = 16; off > 0; off >>= 1) {
        s += __shfl_xor_sync(0xffffffffu, s, off);
        ss += __shfl_xor_sync(0xffffffffu, ss, off);
    }
    if (lane == 0) { sred[wid] = s; ssred[wid] = ss; }
    __syncthreads();
    if (wid == 0) {
        float s2 = (lane < 8) ? sred[lane] : 0.f;
        float ss2 = (lane < 8) ? ssred[lane] : 0.f;
#pragma unroll
        for (int off = 4; off > 0; off >>= 1) {
            s2 += __shfl_xor_sync(0xffffffffu, s2, off);
            ss2 += __shfl_xor_sync(0xffffffffu, ss2, off);
        }
        if (lane == 0) {
            const float mu = s2 * (1.f / D_);
            const float var = ss2 * (1.f / D_) - mu * mu;
            muSh = mu;
            rsSh = rsqrtf(var + 1e-6f);
        }
    }
    __syncthreads();

    const float mu = muSh, rs = rsSh;
    float4 gg = *(const float4*)(g + tid * 4);
    float4 bb = *(const float4*)(be + tid * 4);
    float4 y;
    y.x = (x.x - mu) * rs * gg.x + bb.x;
    y.y = (x.y - mu) * rs * gg.y + bb.y;
    y.z = (x.z - mu) * rs * gg.z + bb.z;
    y.w = (x.w - mu) * rs * gg.w + bb.w;
    *(float4*)(out + (size_t)row * D_ + tid * 4) = y;
    if (outh) {
        *(__half2*)(outh + (size_t)row * D_ + tid * 4)     = __floats2half2_rn(y.x, y.y);
        *(__half2*)(outh + (size_t)row * D_ + tid * 4 + 2) = __floats2half2_rn(y.z, y.w);
    }
}

// ---------------------------------------------------------------------------
// Launch
// ---------------------------------------------------------------------------
extern "C" void kernel_launch(void* const* d_in, const int* in_sizes, int n_in,
                              void* d_out, int out_size)
{
    const float* x   = (const float*)d_in[0];
    const unsigned char* mask = (const unsigned char*)d_in[1];
    const float* wq = (const float*)d_in[2];
    const float* bq = (const float*)d_in[3];
    const float* wk = (const float*)d_in[4];
    const float* bk = (const float*)d_in[5];
    const float* wv = (const float*)d_in[6];
    const float* bv = (const float*)d_in[7];
    const float* wm = (const float*)d_in[8];
    const float* bm = (const float*)d_in[9];
    const float* w1 = (const float*)d_in[10];
    const float* b1 = (const float*)d_in[11];
    const float* w2 = (const float*)d_in[12];
    const float* b2 = (const float*)d_in[13];
    const float* g1  = (const float*)d_in[14];
    const float* be1 = (const float*)d_in[15];
    const float* g2  = (const float*)d_in[16];
    const float* be2 = (const float*)d_in[17];
    float* out = (float*)d_out;

    float *y1, *x1, *bqkv;
    __half *xh, *whqkv, *wh, *qkvh, *ctxh, *x1h, *hbh;
    cudaGetSymbolAddress((void**)&y1, g_y1);
    cudaGetSymbolAddress((void**)&x1, g_x1);
    cudaGetSymbolAddress((void**)&bqkv, g_bqkv);
    cudaGetSymbolAddress((void**)&xh, g_xh);
    cudaGetSymbolAddress((void**)&whqkv, g_whqkv);
    cudaGetSymbolAddress((void**)&wh, g_wh);
    cudaGetSymbolAddress((void**)&qkvh, g_qkvh);
    cudaGetSymbolAddress((void**)&ctxh, g_ctxh);
    cudaGetSymbolAddress((void**)&x1h, g_x1h);
    cudaGetSymbolAddress((void**)&hbh, g_hbh);

    __half* whm = wh;
    __half* wh1 = wh + (size_t)1 * 1024 * 1024;
    __half* wh2 = wh + (size_t)5 * 1024 * 1024;

    cudaFuncSetAttribute(hgemm_kernel<0, true>,  cudaFuncAttributeMaxDynamicSharedMemorySize, GEMM_SMEM_BYTES);
    cudaFuncSetAttribute(hgemm_kernel<1, true>,  cudaFuncAttributeMaxDynamicSharedMemorySize, GEMM_SMEM_BYTES);
    cudaFuncSetAttribute(hgemm_kernel<2, false>, cudaFuncAttributeMaxDynamicSharedMemorySize, GEMM_SMEM_BYTES);
    cudaFuncSetAttribute(flash_fp16_kernel, cudaFuncAttributeMaxDynamicSharedMemorySize, FLASH_SMEM_BYTES);

    const dim3 blk(256);

    // Pre-pass
    f2h_kernel<<<NTOK * D_ / 1024, blk>>>(x, xh);
    packw_kernel<<<12288, blk>>>(wq, wk, wv, wm, w1, w2, whqkv, whm, wh1, wh2);
    packb_kernel<<<3, 1024>>>(bq, bk, bv, bqkv);

    // Packed QKV GEMM
    hgemm_kernel<0, true><<<dim3(QKS / 128, NTOK / 128), blk, GEMM_SMEM_BYTES>>>(
        xh, whqkv, bqkv, nullptr, qkvh, NTOK, QKS, D_);

    // Flash attention -> ctxh
    flash_fp16_kernel<<<dim3(S_ / 128, B_ * H_), blk, FLASH_SMEM_BYTES>>>(qkvh, mask, ctxh);

    // proj + residual -> y1 (fp32)
    hgemm_kernel<2, false><<<dim3(D_ / 128, NTOK / 128), blk, GEMM_SMEM_BYTES>>>(
        ctxh, whm, bm, x, y1, NTOK, D_, D_);
    ln_kernel<<<NTOK, blk>>>(y1, g1, be1, x1, x1h);

    // FFN
    hgemm_kernel<1, true><<<dim3(FF_ / 128, NTOK / 128), blk, GEMM_SMEM_BYTES>>>(
        x1h, wh1, b1, nullptr, hbh, NTOK, FF_, D_);
    hgemm_kernel<2, false><<<dim3(D_ / 128, NTOK / 128), blk, GEMM_SMEM_BYTES>>>(
        hbh, wh2, b2, x1, y1, NTOK, D_, FF_);
    ln_kernel<<<NTOK, blk>>>(y1, g2, be2, out, nullptr);
}

// round 15
// speedup vs baseline: 1.0845x; 1.0845x over previous
#include <cuda_runtime.h>
#include <cuda_fp16.h>
#include <math.h>
#include <stdint.h>

// Problem constants
#define B_   4
#define S_   2048
#define D_   1024
#define H_   16
#define DH_  64
#define FF_  4096
#define NTOK (B_ * S_)   // 8192
#define QKS  3072        // packed qkv row stride

// ---------------------------------------------------------------------------
// Scratch buffers
// ---------------------------------------------------------------------------
__device__ float  g_y1[(size_t)NTOK * D_];
__device__ float  g_x1[(size_t)NTOK * D_];
__device__ float  g_bqkv[QKS];
__device__ __half g_xh[(size_t)NTOK * D_];
__device__ __half g_whqkv[(size_t)D_ * QKS];
__device__ __half g_wh[(size_t)9 * 1024 * 1024];    // wm (1M), w1 (4M), w2 (4M)
__device__ __half g_qkvh[(size_t)NTOK * QKS];       // packed q|k|v fp16
__device__ __half g_ctxh[(size_t)NTOK * D_];
__device__ __half g_x1h[(size_t)NTOK * D_];
__device__ __half g_hbh[(size_t)NTOK * FF_];

// ---------------------------------------------------------------------------
// helpers
// ---------------------------------------------------------------------------
__device__ __forceinline__ void mma_f16(float* d, const uint32_t* a, const uint32_t* b) {
    asm volatile(
        "mma.sync.aligned.m16n8k16.row.col.f32.f16.f16.f32 "
        "{%0,%1,%2,%3}, {%4,%5,%6,%7}, {%8,%9}, {%0,%1,%2,%3};"
        : "+f"(d[0]), "+f"(d[1]), "+f"(d[2]), "+f"(d[3])
        : "r"(a[0]), "r"(a[1]), "r"(a[2]), "r"(a[3]), "r"(b[0]), "r"(b[1]));
}

__device__ __forceinline__ uint32_t smem_u32(const void* p) {
    uint32_t a;
    asm("{ .reg .u64 t; cvta.to.shared.u64 t, %1; cvt.u32.u64 %0, t; }" : "=r"(a) : "l"(p));
    return a;
}

__device__ __forceinline__ void cpasync16(uint32_t dst, const void* src) {
    asm volatile("cp.async.cg.shared.global [%0], [%1], 16;" :: "r"(dst), "l"(src) : "memory");
}
__device__ __forceinline__ void cpasync_commit() {
    asm volatile("cp.async.commit_group;" ::: "memory");
}
template <int N>
__device__ __forceinline__ void cpasync_wait() {
    asm volatile("cp.async.wait_group %0;" :: "n"(N) : "memory");
}

__device__ __forceinline__ void ldsm_x4(uint32_t* r, uint32_t addr) {
    asm volatile("ldmatrix.sync.aligned.m8n8.x4.shared.b16 {%0,%1,%2,%3}, [%4];"
                 : "=r"(r[0]), "=r"(r[1]), "=r"(r[2]), "=r"(r[3]) : "r"(addr));
}
__device__ __forceinline__ void ldsm_x4_t(uint32_t* r, uint32_t addr) {
    asm volatile("ldmatrix.sync.aligned.m8n8.x4.trans.shared.b16 {%0,%1,%2,%3}, [%4];"
                 : "=r"(r[0]), "=r"(r[1]), "=r"(r[2]), "=r"(r[3]) : "r"(addr));
}

__device__ __forceinline__ uint32_t h2u(__half2 h) {
    return *reinterpret_cast<uint32_t*>(&h);
}

// ---------------------------------------------------------------------------
// Pre-pass kernels
// ---------------------------------------------------------------------------
__global__ __launch_bounds__(256) void f2h_kernel(
    const float* __restrict__ src, __half* __restrict__ dst)
{
    const int i = (blockIdx.x * 256 + threadIdx.x) * 4;
    float4 v = *(const float4*)(src + i);
    *(__half2*)(dst + i)     = __floats2half2_rn(v.x, v.y);
    *(__half2*)(dst + i + 2) = __floats2half2_rn(v.z, v.w);
}

__global__ __launch_bounds__(256) void packw_kernel(
    const float* __restrict__ wq, const float* __restrict__ wk,
    const float* __restrict__ wv, const float* __restrict__ wm,
    const float* __restrict__ w1, const float* __restrict__ w2,
    __half* __restrict__ whqkv, __half* __restrict__ whm,
    __half* __restrict__ wh1, __half* __restrict__ wh2)
{
    const int bid = blockIdx.x;
    if (bid < 3072) {
        const int y = bid >> 10;
        const int i = ((bid & 1023) * 256 + threadIdx.x) * 4;
        const float* src = (y == 0) ? wq : (y == 1) ? wk : wv;
        float4 v = *(const float4*)(src + i);
        __half* o = whqkv + (size_t)(i >> 10) * QKS + y * 1024 + (i & 1023);
        *(__half2*)o       = __floats2half2_rn(v.x, v.y);
        *(__half2*)(o + 2) = __floats2half2_rn(v.z, v.w);
    } else if (bid < 4096) {
        const int i = ((bid - 3072) * 256 + threadIdx.x) * 4;
        float4 v = *(const float4*)(wm + i);
        *(__half2*)(whm + i)     = __floats2half2_rn(v.x, v.y);
        *(__half2*)(whm + i + 2) = __floats2half2_rn(v.z, v.w);
    } else if (bid < 8192) {
        const int i = ((bid - 4096) * 256 + threadIdx.x) * 4;
        float4 v = *(const float4*)(w1 + i);
        *(__half2*)(wh1 + i)     = __floats2half2_rn(v.x, v.y);
        *(__half2*)(wh1 + i + 2) = __floats2half2_rn(v.z, v.w);
    } else {
        const int i = ((bid - 8192) * 256 + threadIdx.x) * 4;
        float4 v = *(const float4*)(w2 + i);
        *(__half2*)(wh2 + i)     = __floats2half2_rn(v.x, v.y);
        *(__half2*)(wh2 + i + 2) = __floats2half2_rn(v.z, v.w);
    }
}

__global__ __launch_bounds__(1024) void packb_kernel(
    const float* __restrict__ bq, const float* __restrict__ bk,
    const float* __restrict__ bv, float* __restrict__ out)
{
    const int i = blockIdx.x * 1024 + threadIdx.x;
    out[i] = (i < 1024) ? bq[i] : (i < 2048) ? bk[i - 1024] : bv[i - 2048];
}

// ---------------------------------------------------------------------------
// fp16 GEMM: GK=32, 5-stage cp.async + ldmatrix, 2 CTA/SM, one sync/iter.
// (round-13 validated config, pipeline deepened 4 -> 5 stages)
// A stage [128][32] halfs (64B rows, swz chunk^((row>>1)&3))
// B stage [32][128] halfs (256B rows, swz chunk^(krow&7))
// ---------------------------------------------------------------------------
#define GK 32
#define ASTG (128 * 32)
#define BSTG (32 * 128)
#define STGH (ASTG + BSTG)              // 8192 halfs = 16 KB
#define NSTG 5
#define GEMM_SMEM_BYTES (NSTG * STGH * 2)   // 81920

template <int EPI, bool HOUT>
__device__ __forceinline__ void hgemm_body(
    const __half* __restrict__ A, const __half* __restrict__ W,
    const float* __restrict__ bias, const float* __restrict__ res,
    void* __restrict__ Cv, int M, int N, int K)
{
    extern __shared__ __half hsm[];
    const uint32_t sbase = smem_u32(hsm);

    const int tid = threadIdx.x;
    const int lane = tid & 31;
    const int warp = tid >> 5;
    const int wm = warp >> 2;
    const int wn = warp & 3;
    const int bm = blockIdx.y * 128;
    const int bn = blockIdx.x * 128;

    const int ar0 = tid >> 2;
    const int akc = tid & 3;
    const int bkr = tid >> 4;
    const int bnc = tid & 15;

    const __half* Ag = A + (size_t)bm * K;
    const __half* Wg = W + bn;

    const uint32_t a_off1 = (uint32_t)(ar0 * 64 + ((akc ^ ((ar0 >> 1) & 3)) << 4));
    const uint32_t a_off2 = (uint32_t)((ar0 + 64) * 64 + ((akc ^ (((ar0 + 64) >> 1) & 3)) << 4));
    const uint32_t b_off1 = (uint32_t)(bkr * 256 + ((bnc ^ (bkr & 7)) << 4));
    const uint32_t b_off2 = (uint32_t)((bkr + 16) * 256 + ((bnc ^ ((bkr + 16) & 7)) << 4));

    uint32_t a_row_off[4];
    int a_row_sw[4];
#pragma unroll
    for (int i = 0; i < 4; i++) {
        const int row = wm * 64 + i * 16 + (lane & 15);
        a_row_off[i] = (uint32_t)(row * 64);
        a_row_sw[i] = (row >> 1) & 3;
    }
    const int a_csel = lane >> 4;
    const int b_krlo = lane & 15;
    const int b_ncsel = wn * 4 + (lane >> 4);

    float acc[4][4][4];
#pragma unroll
    for (int i = 0; i < 4; i++)
#pragma unroll
        for (int j = 0; j < 4; j++)
#pragma unroll
            for (int r = 0; r < 4; r++) acc[i][j][r] = 0.f;

    const int NIT = K / GK;

    auto issue = [&](int s, int k0) {
        const uint32_t ab = sbase + (uint32_t)(s * STGH) * 2;
        const uint32_t bb = ab + ASTG * 2;
        cpasync16(ab + a_off1, Ag + (size_t)ar0 * K + k0 + akc * 8);
        cpasync16(ab + a_off2, Ag + (size_t)(ar0 + 64) * K + k0 + akc * 8);
        cpasync16(bb + b_off1, Wg + (size_t)(k0 + bkr) * N + bnc * 8);
        cpasync16(bb + b_off2, Wg + (size_t)(k0 + bkr + 16) * N + bnc * 8);
        cpasync_commit();
    };

    // prologue: 4 groups in flight
    issue(0, 0);
    issue(1, GK);
    issue(2, 2 * GK);
    issue(3, 3 * GK);

    int stage = 0;
    int nstage = 4;  // next stage to fill (== (t+4) % NSTG tracked incrementally)
    for (int t = 0; t < NIT; t++) {
        // ensure group t complete; allowed pending = min(3, NIT-1-t)
        if (t + 3 < NIT) cpasync_wait<3>();
        else if (t + 2 < NIT) cpasync_wait<2>();
        else if (t + 1 < NIT) cpasync_wait<1>();
        else cpasync_wait<0>();
        __syncthreads();
        if (t + 4 < NIT) {
            issue(nstage, (t + 4) * GK);
            if (++nstage == NSTG) nstage = 0;
        }

        const uint32_t ab = sbase + (uint32_t)(stage * STGH) * 2;
        const uint32_t bb = ab + ASTG * 2;

#pragma unroll
        for (int ksb = 0; ksb < 2; ksb++) {
            uint32_t av[4][4];
#pragma unroll
            for (int i = 0; i < 4; i++) {
                const int lch = ksb * 2 + a_csel;
                ldsm_x4(av[i], ab + a_row_off[i] + (uint32_t)((lch ^ a_row_sw[i]) << 4));
            }
            uint32_t bf[4][2];
#pragma unroll
            for (int jj = 0; jj < 2; jj++) {
                uint32_t tmp[4];
                const int krow = ksb * 16 + b_krlo;
                const int nch = b_ncsel + jj * 2;
                ldsm_x4_t(tmp, bb + (uint32_t)(krow * 256) + (uint32_t)((nch ^ (krow & 7)) << 4));
                bf[jj * 2][0] = tmp[0]; bf[jj * 2][1] = tmp[1];
                bf[jj * 2 + 1][0] = tmp[2]; bf[jj * 2 + 1][1] = tmp[3];
            }
#pragma unroll
            for (int i = 0; i < 4; i++)
#pragma unroll
                for (int j = 0; j < 4; j++)
                    mma_f16(acc[i][j], av[i], bf[j]);
        }
        if (++stage == NSTG) stage = 0;
    }

#pragma unroll
    for (int i = 0; i < 4; i++) {
        const int r0 = bm + wm * 64 + i * 16 + (lane >> 2);
#pragma unroll
        for (int j = 0; j < 4; j++) {
            const int col = bn + wn * 32 + j * 8 + (lane & 3) * 2;
            float2 bi = *(const float2*)(bias + col);
            float o00 = acc[i][j][0] + bi.x;
            float o01 = acc[i][j][1] + bi.y;
            float o10 = acc[i][j][2] + bi.x;
            float o11 = acc[i][j][3] + bi.y;
            if (EPI == 1) {
                o00 = fmaxf(o00, 0.f); o01 = fmaxf(o01, 0.f);
                o10 = fmaxf(o10, 0.f); o11 = fmaxf(o11, 0.f);
            }
            if (EPI == 2) {
                float2 r0v = *(const float2*)(res + (size_t)r0 * N + col);
                float2 r1v = *(const float2*)(res + (size_t)(r0 + 8) * N + col);
                o00 += r0v.x; o01 += r0v.y;
                o10 += r1v.x; o11 += r1v.y;
            }
            if (HOUT) {
                __half* Ch = (__half*)Cv;
                *(__half2*)(Ch + (size_t)r0 * N + col) = __floats2half2_rn(o00, o01);
                *(__half2*)(Ch + (size_t)(r0 + 8) * N + col) = __floats2half2_rn(o10, o11);
            } else {
                float* Cf = (float*)Cv;
                *(float2*)(Cf + (size_t)r0 * N + col) = make_float2(o00, o01);
                *(float2*)(Cf + (size_t)(r0 + 8) * N + col) = make_float2(o10, o11);
            }
        }
    }
}

template <int EPI, bool HOUT>
__global__ __launch_bounds__(256, 2) void hgemm_kernel(
    const __half* __restrict__ A, const __half* __restrict__ W,
    const float* __restrict__ bias, const float* __restrict__ res,
    void* __restrict__ C, int M, int N, int K)
{
    hgemm_body<EPI, HOUT>(A, W, bias, res, C, M, N, K);
}

// ---------------------------------------------------------------------------
// fp16 flash attention (round-13 validated, unchanged)
// ---------------------------------------------------------------------------
#define FBK 64
#define KROW 72
#define KBUF (64 * KROW)
#define NSTAGE 3
#define FLASH_SMEM_BYTES (NSTAGE * 2 * KBUF * 2)

__global__ __launch_bounds__(256, 2) void flash_fp16_kernel(
    const __half* __restrict__ qkv, const unsigned char* __restrict__ mask,
    __half* __restrict__ ctxh)
{
    extern __shared__ __half fh[];
    const uint32_t ks_u = smem_u32(fh);
    const uint32_t vs_u = ks_u + NSTAGE * KBUF * 2;

    const int tid = threadIdx.x;
    const int lane = tid & 31;
    const int warp = tid >> 5;
    const int bh = blockIdx.y;
    const int b = bh >> 4;
    const int h = bh & 15;
    const int q0 = blockIdx.x * 128;
    const int hoff = h * DH_;
    const unsigned char* mrow = mask + (size_t)b * S_;

    const int r0 = lane >> 2;
    const int c0 = lane & 3;
    const int lrow = lane & 15;
    const int lhi = lane >> 4;

    uint32_t qf[4][4];
    {
        const size_t rowa = (size_t)(b * S_ + q0 + warp * 16 + r0) * QKS + hoff;
#pragma unroll
        for (int ks = 0; ks < 4; ks++) {
            const int c = ks * 16 + 2 * c0;
            qf[ks][0] = *(const uint32_t*)(qkv + rowa + c);
            qf[ks][1] = *(const uint32_t*)(qkv + rowa + (size_t)8 * QKS + c);
            qf[ks][2] = *(const uint32_t*)(qkv + rowa + c + 8);
            qf[ks][3] = *(const uint32_t*)(qkv + rowa + (size_t)8 * QKS + c + 8);
        }
    }

    float oa[8][4];
    float mx0 = -1e30f, mx1 = -1e30f, l0 = 0.f, l1 = 0.f;
#pragma unroll
    for (int j = 0; j < 8; j++)
#pragma unroll
        for (int r = 0; r < 4; r++) oa[j][r] = 0.f;

    const int id0 = tid, id1 = tid + 256;
    const int krow0 = id0 >> 3, kch0 = id0 & 7;
    const int krow1 = id1 >> 3, kch1 = id1 & 7;

    const __half* kbase = qkv + (size_t)b * S_ * QKS + 1024 + hoff;
    const __half* vbase = qkv + (size_t)b * S_ * QKS + 2048 + hoff;

    const int NT = S_ / FBK;

    auto issue = [&](int st, int kt) {
        const uint32_t kdst = ks_u + (uint32_t)(st * KBUF) * 2;
        const uint32_t vdst = vs_u + (uint32_t)(st * KBUF) * 2;
        cpasync16(kdst + (uint32_t)(krow0 * KROW) * 2 + kch0 * 16,
                  kbase + (size_t)(kt + krow0) * QKS + kch0 * 8);
        cpasync16(kdst + (uint32_t)(krow1 * KROW) * 2 + kch1 * 16,
                  kbase + (size_t)(kt + krow1) * QKS + kch1 * 8);
        cpasync16(vdst + (uint32_t)(krow0 * KROW) * 2 + kch0 * 16,
                  vbase + (size_t)(kt + krow0) * QKS + kch0 * 8);
        cpasync16(vdst + (uint32_t)(krow1 * KROW) * 2 + kch1 * 16,
                  vbase + (size_t)(kt + krow1) * QKS + kch1 * 8);
        cpasync_commit();
    };

    issue(0, 0);
    issue(1, FBK);

    for (int t = 0; t < NT; t++) {
        const int kt = t * FBK;
        if (t + 1 < NT) cpasync_wait<1>();
        else cpasync_wait<0>();
        __syncthreads();
        if (t + 2 < NT) issue((t + 2) % NSTAGE, kt + 2 * FBK);

        const uint32_t kc_u = ks_u + (uint32_t)((t % NSTAGE) * KBUF) * 2;
        const uint32_t vc_u = vs_u + (uint32_t)((t % NSTAGE) * KBUF) * 2;

        float sa[8][4];
#pragma unroll
        for (int j = 0; j < 8; j++)
#pragma unroll
            for (int r = 0; r < 4; r++) sa[j][r] = 0.f;

#pragma unroll
        for (int ks = 0; ks < 4; ks++) {
#pragma unroll
            for (int jp = 0; jp < 4; jp++) {
                uint32_t kv4[4];
                ldsm_x4(kv4, kc_u + (uint32_t)(((jp * 16 + lrow) * KROW + ks * 16 + lhi * 8) * 2));
                uint32_t b0[2] = {kv4[0], kv4[2]};
                uint32_t b1[2] = {kv4[1], kv4[3]};
                mma_f16(sa[2 * jp], qf[ks], b0);
                mma_f16(sa[2 * jp + 1], qf[ks], b1);
            }
        }

        float rm0 = -1e30f, rm1 = -1e30f;
#pragma unroll
        for (int j = 0; j < 8; j++) {
            const int col = kt + j * 8 + 2 * c0;
            const bool m0 = mrow[col] != 0;
            const bool m1 = mrow[col + 1] != 0;
            sa[j][0] = m0 ? -1e9f : sa[j][0] * 0.125f;
            sa[j][1] = m1 ? -1e9f : sa[j][1] * 0.125f;
            sa[j][2] = m0 ? -1e9f : sa[j][2] * 0.125f;
            sa[j][3] = m1 ? -1e9f : sa[j][3] * 0.125f;
            rm0 = fmaxf(rm0, fmaxf(sa[j][0], sa[j][1]));
            rm1 = fmaxf(rm1, fmaxf(sa[j][2], sa[j][3]));
        }
        rm0 = fmaxf(rm0, __shfl_xor_sync(0xffffffffu, rm0, 1));
        rm0 = fmaxf(rm0, __shfl_xor_sync(0xffffffffu, rm0, 2));
        rm1 = fmaxf(rm1, __shfl_xor_sync(0xffffffffu, rm1, 1));
        rm1 = fmaxf(rm1, __shfl_xor_sync(0xffffffffu, rm1, 2));

        const float mn0 = fmaxf(mx0, rm0);
        const float mn1 = fmaxf(mx1, rm1);
        const float corr0 = __expf(mx0 - mn0);
        const float corr1 = __expf(mx1 - mn1);
        mx0 = mn0; mx1 = mn1;

        float rs0 = 0.f, rs1 = 0.f;
#pragma unroll
        for (int j = 0; j < 8; j++) {
            sa[j][0] = __expf(sa[j][0] - mn0);
            sa[j][1] = __expf(sa[j][1] - mn0);
            sa[j][2] = __expf(sa[j][2] - mn1);
            sa[j][3] = __expf(sa[j][3] - mn1);
            rs0 += sa[j][0] + sa[j][1];
            rs1 += sa[j][2] + sa[j][3];
            oa[j][0] *= corr0; oa[j][1] *= corr0;
            oa[j][2] *= corr1; oa[j][3] *= corr1;
        }
        rs0 += __shfl_xor_sync(0xffffffffu, rs0, 1);
        rs0 += __shfl_xor_sync(0xffffffffu, rs0, 2);
        rs1 += __shfl_xor_sync(0xffffffffu, rs1, 1);
        rs1 += __shfl_xor_sync(0xffffffffu, rs1, 2);
        l0 = l0 * corr0 + rs0;
        l1 = l1 * corr1 + rs1;

#pragma unroll
        for (int ks = 0; ks < 4; ks++) {
            uint32_t pf[4];
            pf[0] = h2u(__floats2half2_rn(sa[2 * ks][0], sa[2 * ks][1]));
            pf[1] = h2u(__floats2half2_rn(sa[2 * ks][2], sa[2 * ks][3]));
            pf[2] = h2u(__floats2half2_rn(sa[2 * ks + 1][0], sa[2 * ks + 1][1]));
            pf[3] = h2u(__floats2half2_rn(sa[2 * ks + 1][2], sa[2 * ks + 1][3]));
#pragma unroll
            for (int q = 0; q < 4; q++) {
                uint32_t t4[4];
                ldsm_x4_t(t4, vc_u + (uint32_t)(((ks * 16 + lrow) * KROW + (2 * q + lhi) * 8) * 2));
                mma_f16(oa[2 * q], pf, t4);
                mma_f16(oa[2 * q + 1], pf, t4 + 2);
            }
        }
    }

    const float inv0 = 1.f / l0;
    const float inv1 = 1.f / l1;
    const int row0 = q0 + warp * 16 + r0;
    const size_t obase = (size_t)b * S_ * D_ + hoff;
#pragma unroll
    for (int j = 0; j < 8; j++) {
        const int col = j * 8 + 2 * c0;
        *(__half2*)(ctxh + obase + (size_t)row0 * D_ + col) =
            __floats2half2_rn(oa[j][0] * inv0, oa[j][1] * inv0);
        *(__half2*)(ctxh + obase + (size_t)(row0 + 8) * D_ + col) =
            __floats2half2_rn(oa[j][2] * inv1, oa[j][3] * inv1);
    }
}

// ---------------------------------------------------------------------------
// LayerNorm
// ---------------------------------------------------------------------------
__global__ __launch_bounds__(256) void ln_kernel(
    const float* __restrict__ in, const float* __restrict__ g,
    const float* __restrict__ be, float* __restrict__ out,
    __half* __restrict__ outh)
{
    __shared__ float sred[8], ssred[8];
    __shared__ float muSh, rsSh;

    const int row = blockIdx.x;
    const int tid = threadIdx.x;
    const int lane = tid & 31;
    const int wid = tid >> 5;

    const float* p = in + (size_t)row * D_;
    float4 x = *(const float4*)(p + tid * 4);
    float s = x.x + x.y + x.z + x.w;
    float ss = x.x * x.x + x.y * x.y + x.z * x.z + x.w * x.w;

#pragma unroll
    for (int off = 16; off > 0; off >>= 1) {
        s += __shfl_xor_sync(0xffffffffu, s, off);
        ss += __shfl_xor_sync(0xffffffffu, ss, off);
    }
    if (lane == 0) { sred[wid] = s; ssred[wid] = ss; }
    __syncthreads();
    if (wid == 0) {
        float s2 = (lane < 8) ? sred[lane] : 0.f;
        float ss2 = (lane < 8) ? ssred[lane] : 0.f;
#pragma unroll
        for (int off = 4; off > 0; off >>= 1) {
            s2 += __shfl_xor_sync(0xffffffffu, s2, off);
            ss2 += __shfl_xor_sync(0xffffffffu, ss2, off);
        }
        if (lane == 0) {
            const float mu = s2 * (1.f / D_);
            const float var = ss2 * (1.f / D_) - mu * mu;
            muSh = mu;
            rsSh = rsqrtf(var + 1e-6f);
        }
    }
    __syncthreads();

    const float mu = muSh, rs = rsSh;
    float4 gg = *(const float4*)(g + tid * 4);
    float4 bb = *(const float4*)(be + tid * 4);
    float4 y;
    y.x = (x.x - mu) * rs * gg.x + bb.x;
    y.y = (x.y - mu) * rs * gg.y + bb.y;
    y.z = (x.z - mu) * rs * gg.z + bb.z;
    y.w = (x.w - mu) * rs * gg.w + bb.w;
    *(float4*)(out + (size_t)row * D_ + tid * 4) = y;
    if (outh) {
        *(__half2*)(outh + (size_t)row * D_ + tid * 4)     = __floats2half2_rn(y.x, y.y);
        *(__half2*)(outh + (size_t)row * D_ + tid * 4 + 2) = __floats2half2_rn(y.z, y.w);
    }
}

// ---------------------------------------------------------------------------
// Launch
// ---------------------------------------------------------------------------
extern "C" void kernel_launch(void* const* d_in, const int* in_sizes, int n_in,
                              void* d_out, int out_size)
{
    const float* x   = (const float*)d_in[0];
    const unsigned char* mask = (const unsigned char*)d_in[1];
    const float* wq = (const float*)d_in[2];
    const float* bq = (const float*)d_in[3];
    const float* wk = (const float*)d_in[4];
    const float* bk = (const float*)d_in[5];
    const float* wv = (const float*)d_in[6];
    const float* bv = (const float*)d_in[7];
    const float* wm = (const float*)d_in[8];
    const float* bm = (const float*)d_in[9];
    const float* w1 = (const float*)d_in[10];
    const float* b1 = (const float*)d_in[11];
    const float* w2 = (const float*)d_in[12];
    const float* b2 = (const float*)d_in[13];
    const float* g1  = (const float*)d_in[14];
    const float* be1 = (const float*)d_in[15];
    const float* g2  = (const float*)d_in[16];
    const float* be2 = (const float*)d_in[17];
    float* out = (float*)d_out;

    float *y1, *x1, *bqkv;
    __half *xh, *whqkv, *wh, *qkvh, *ctxh, *x1h, *hbh;
    cudaGetSymbolAddress((void**)&y1, g_y1);
    cudaGetSymbolAddress((void**)&x1, g_x1);
    cudaGetSymbolAddress((void**)&bqkv, g_bqkv);
    cudaGetSymbolAddress((void**)&xh, g_xh);
    cudaGetSymbolAddress((void**)&whqkv, g_whqkv);
    cudaGetSymbolAddress((void**)&wh, g_wh);
    cudaGetSymbolAddress((void**)&qkvh, g_qkvh);
    cudaGetSymbolAddress((void**)&ctxh, g_ctxh);
    cudaGetSymbolAddress((void**)&x1h, g_x1h);
    cudaGetSymbolAddress((void**)&hbh, g_hbh);

    __half* whm = wh;
    __half* wh1 = wh + (size_t)1 * 1024 * 1024;
    __half* wh2 = wh + (size_t)5 * 1024 * 1024;

    cudaFuncSetAttribute(hgemm_kernel<0, true>,  cudaFuncAttributeMaxDynamicSharedMemorySize, GEMM_SMEM_BYTES);
    cudaFuncSetAttribute(hgemm_kernel<1, true>,  cudaFuncAttributeMaxDynamicSharedMemorySize, GEMM_SMEM_BYTES);
    cudaFuncSetAttribute(hgemm_kernel<2, false>, cudaFuncAttributeMaxDynamicSharedMemorySize, GEMM_SMEM_BYTES);
    cudaFuncSetAttribute(flash_fp16_kernel, cudaFuncAttributeMaxDynamicSharedMemorySize, FLASH_SMEM_BYTES);

    const dim3 blk(256);

    // Pre-pass
    f2h_kernel<<<NTOK * D_ / 1024, blk>>>(x, xh);
    packw_kernel<<<12288, blk>>>(wq, wk, wv, wm, w1, w2, whqkv, whm, wh1, wh2);
    packb_kernel<<<3, 1024>>>(bq, bk, bv, bqkv);

    // Packed QKV GEMM
    hgemm_kernel<0, true><<<dim3(QKS / 128, NTOK / 128), blk, GEMM_SMEM_BYTES>>>(
        xh, whqkv, bqkv, nullptr, qkvh, NTOK, QKS, D_);

    // Flash attention -> ctxh
    flash_fp16_kernel<<<dim3(S_ / 128, B_ * H_), blk, FLASH_SMEM_BYTES>>>(qkvh, mask, ctxh);

    // proj + residual -> y1 (fp32)
    hgemm_kernel<2, false><<<dim3(D_ / 128, NTOK / 128), blk, GEMM_SMEM_BYTES>>>(
        ctxh, whm, bm, x, y1, NTOK, D_, D_);
    ln_kernel<<<NTOK, blk>>>(y1, g1, be1, x1, x1h);

    // FFN
    hgemm_kernel<1, true><<<dim3(FF_ / 128, NTOK / 128), blk, GEMM_SMEM_BYTES>>>(
        x1h, wh1, b1, nullptr, hbh, NTOK, FF_, D_);
    hgemm_kernel<2, false><<<dim3(D_ / 128, NTOK / 128), blk, GEMM_SMEM_BYTES>>>(
        hbh, wh2, b2, x1, y1, NTOK, D_, FF_);
    ln_kernel<<<NTOK, blk>>>(y1, g2, be2, out, nullptr);
}

// round 16
// speedup vs baseline: 1.0900x; 1.0050x over previous
#include <cuda_runtime.h>
#include <cuda_fp16.h>
#include <math.h>
#include <stdint.h>

// Problem constants
#define B_   4
#define S_   2048
#define D_   1024
#define H_   16
#define DH_  64
#define FF_  4096
#define NTOK (B_ * S_)   // 8192
#define QKS  3072        // packed qkv row stride

// ---------------------------------------------------------------------------
// Scratch buffers
// ---------------------------------------------------------------------------
__device__ float  g_y1[(size_t)NTOK * D_];
__device__ float  g_x1[(size_t)NTOK * D_];
__device__ float  g_bqkv[QKS];
__device__ __half g_xh[(size_t)NTOK * D_];
__device__ __half g_whqkv[(size_t)D_ * QKS];
__device__ __half g_wh[(size_t)9 * 1024 * 1024];    // wm (1M), w1 (4M), w2 (4M)
__device__ __half g_qkvh[(size_t)NTOK * QKS];       // packed q|k|v fp16
__device__ __half g_ctxh[(size_t)NTOK * D_];
__device__ __half g_x1h[(size_t)NTOK * D_];
__device__ __half g_hbh[(size_t)NTOK * FF_];

// ---------------------------------------------------------------------------
// helpers
// ---------------------------------------------------------------------------
__device__ __forceinline__ void mma_f16(float* d, const uint32_t* a, const uint32_t* b) {
    asm volatile(
        "mma.sync.aligned.m16n8k16.row.col.f32.f16.f16.f32 "
        "{%0,%1,%2,%3}, {%4,%5,%6,%7}, {%8,%9}, {%0,%1,%2,%3};"
        : "+f"(d[0]), "+f"(d[1]), "+f"(d[2]), "+f"(d[3])
        : "r"(a[0]), "r"(a[1]), "r"(a[2]), "r"(a[3]), "r"(b[0]), "r"(b[1]));
}

__device__ __forceinline__ uint32_t smem_u32(const void* p) {
    uint32_t a;
    asm("{ .reg .u64 t; cvta.to.shared.u64 t, %1; cvt.u32.u64 %0, t; }" : "=r"(a) : "l"(p));
    return a;
}

__device__ __forceinline__ void cpasync16(uint32_t dst, const void* src) {
    asm volatile("cp.async.cg.shared.global [%0], [%1], 16;" :: "r"(dst), "l"(src) : "memory");
}
__device__ __forceinline__ void cpasync_commit() {
    asm volatile("cp.async.commit_group;" ::: "memory");
}
template <int N>
__device__ __forceinline__ void cpasync_wait() {
    asm volatile("cp.async.wait_group %0;" :: "n"(N) : "memory");
}

__device__ __forceinline__ void ldsm_x4(uint32_t* r, uint32_t addr) {
    asm volatile("ldmatrix.sync.aligned.m8n8.x4.shared.b16 {%0,%1,%2,%3}, [%4];"
                 : "=r"(r[0]), "=r"(r[1]), "=r"(r[2]), "=r"(r[3]) : "r"(addr));
}
__device__ __forceinline__ void ldsm_x4_t(uint32_t* r, uint32_t addr) {
    asm volatile("ldmatrix.sync.aligned.m8n8.x4.trans.shared.b16 {%0,%1,%2,%3}, [%4];"
                 : "=r"(r[0]), "=r"(r[1]), "=r"(r[2]), "=r"(r[3]) : "r"(addr));
}

__device__ __forceinline__ uint32_t h2u(__half2 h) {
    return *reinterpret_cast<uint32_t*>(&h);
}

// ---------------------------------------------------------------------------
// Pre-pass kernels
// prep_main: blocks [0,8192): f2h(x); [8192,11264): pack qkv weights;
//            [11264,11267): bias pack.
// prep_rest: blocks [0,1024): wm; [1024,5120): w1; [5120,9216): w2.
// ---------------------------------------------------------------------------
__global__ __launch_bounds__(256) void prep_main_kernel(
    const float* __restrict__ x, __half* __restrict__ xh,
    const float* __restrict__ wq, const float* __restrict__ wk,
    const float* __restrict__ wv, __half* __restrict__ whqkv,
    const float* __restrict__ bq, const float* __restrict__ bk,
    const float* __restrict__ bv, float* __restrict__ bqkv)
{
    const int bid = blockIdx.x;
    if (bid < 8192) {
        const int i = (bid * 256 + threadIdx.x) * 4;
        float4 v = *(const float4*)(x + i);
        *(__half2*)(xh + i)     = __floats2half2_rn(v.x, v.y);
        *(__half2*)(xh + i + 2) = __floats2half2_rn(v.z, v.w);
    } else if (bid < 11264) {
        const int pb = bid - 8192;
        const int y = pb >> 10;
        const int i = ((pb & 1023) * 256 + threadIdx.x) * 4;
        const float* src = (y == 0) ? wq : (y == 1) ? wk : wv;
        float4 v = *(const float4*)(src + i);
        __half* o = whqkv + (size_t)(i >> 10) * QKS + y * 1024 + (i & 1023);
        *(__half2*)o       = __floats2half2_rn(v.x, v.y);
        *(__half2*)(o + 2) = __floats2half2_rn(v.z, v.w);
    } else {
        const int i = (bid - 11264) * 256 + threadIdx.x;  // 0..767 -> need 3072
#pragma unroll
        for (int r = 0; r < 4; r++) {
            const int j = i * 4 + r;
            bqkv[j] = (j < 1024) ? bq[j] : (j < 2048) ? bk[j - 1024] : bv[j - 2048];
        }
    }
}

__global__ __launch_bounds__(256) void prep_rest_kernel(
    const float* __restrict__ wm, const float* __restrict__ w1,
    const float* __restrict__ w2, __half* __restrict__ whm,
    __half* __restrict__ wh1, __half* __restrict__ wh2)
{
    const int bid = blockIdx.x;
    const float* src;
    __half* dst;
    int i;
    if (bid < 1024) { src = wm; dst = whm; i = (bid * 256 + threadIdx.x) * 4; }
    else if (bid < 5120) { src = w1; dst = wh1; i = ((bid - 1024) * 256 + threadIdx.x) * 4; }
    else { src = w2; dst = wh2; i = ((bid - 5120) * 256 + threadIdx.x) * 4; }
    float4 v = *(const float4*)(src + i);
    *(__half2*)(dst + i)     = __floats2half2_rn(v.x, v.y);
    *(__half2*)(dst + i + 2) = __floats2half2_rn(v.z, v.w);
}

// ---------------------------------------------------------------------------
// fp16 GEMM (round-13 validated): GK=32, 4-stage cp.async + ldmatrix,
// 2 CTA/SM, one sync per iteration.
// ---------------------------------------------------------------------------
#define GK 32
#define ASTG (128 * 32)
#define BSTG (32 * 128)
#define STGH (ASTG + BSTG)
#define NSTG 4
#define GEMM_SMEM_BYTES (NSTG * STGH * 2)   // 65536

template <int EPI, bool HOUT>
__device__ __forceinline__ void hgemm_body(
    const __half* __restrict__ A, const __half* __restrict__ W,
    const float* __restrict__ bias, const float* __restrict__ res,
    void* __restrict__ Cv, int M, int N, int K)
{
    extern __shared__ __half hsm[];
    const uint32_t sbase = smem_u32(hsm);

    const int tid = threadIdx.x;
    const int lane = tid & 31;
    const int warp = tid >> 5;
    const int wm = warp >> 2;
    const int wn = warp & 3;
    const int bm = blockIdx.y * 128;
    const int bn = blockIdx.x * 128;

    const int ar0 = tid >> 2;
    const int akc = tid & 3;
    const int bkr = tid >> 4;
    const int bnc = tid & 15;

    const __half* Ag = A + (size_t)bm * K;
    const __half* Wg = W + bn;

    const uint32_t a_off1 = (uint32_t)(ar0 * 64 + ((akc ^ ((ar0 >> 1) & 3)) << 4));
    const uint32_t a_off2 = (uint32_t)((ar0 + 64) * 64 + ((akc ^ (((ar0 + 64) >> 1) & 3)) << 4));
    const uint32_t b_off1 = (uint32_t)(bkr * 256 + ((bnc ^ (bkr & 7)) << 4));
    const uint32_t b_off2 = (uint32_t)((bkr + 16) * 256 + ((bnc ^ ((bkr + 16) & 7)) << 4));

    uint32_t a_row_off[4];
    int a_row_sw[4];
#pragma unroll
    for (int i = 0; i < 4; i++) {
        const int row = wm * 64 + i * 16 + (lane & 15);
        a_row_off[i] = (uint32_t)(row * 64);
        a_row_sw[i] = (row >> 1) & 3;
    }
    const int a_csel = lane >> 4;
    const int b_krlo = lane & 15;
    const int b_ncsel = wn * 4 + (lane >> 4);

    float acc[4][4][4];
#pragma unroll
    for (int i = 0; i < 4; i++)
#pragma unroll
        for (int j = 0; j < 4; j++)
#pragma unroll
            for (int r = 0; r < 4; r++) acc[i][j][r] = 0.f;

    const int NIT = K / GK;

    auto issue = [&](int s, int k0) {
        const uint32_t ab = sbase + (uint32_t)(s * STGH) * 2;
        const uint32_t bb = ab + ASTG * 2;
        cpasync16(ab + a_off1, Ag + (size_t)ar0 * K + k0 + akc * 8);
        cpasync16(ab + a_off2, Ag + (size_t)(ar0 + 64) * K + k0 + akc * 8);
        cpasync16(bb + b_off1, Wg + (size_t)(k0 + bkr) * N + bnc * 8);
        cpasync16(bb + b_off2, Wg + (size_t)(k0 + bkr + 16) * N + bnc * 8);
        cpasync_commit();
    };

    issue(0, 0);
    issue(1, GK);
    issue(2, 2 * GK);

    for (int t = 0; t < NIT; t++) {
        if (t + 2 < NIT) cpasync_wait<2>();
        else if (t + 1 < NIT) cpasync_wait<1>();
        else cpasync_wait<0>();
        __syncthreads();
        if (t + 3 < NIT) issue((t + 3) & 3, (t + 3) * GK);

        const uint32_t ab = sbase + (uint32_t)((t & 3) * STGH) * 2;
        const uint32_t bb = ab + ASTG * 2;

#pragma unroll
        for (int ksb = 0; ksb < 2; ksb++) {
            uint32_t av[4][4];
#pragma unroll
            for (int i = 0; i < 4; i++) {
                const int lch = ksb * 2 + a_csel;
                ldsm_x4(av[i], ab + a_row_off[i] + (uint32_t)((lch ^ a_row_sw[i]) << 4));
            }
            uint32_t bf[4][2];
#pragma unroll
            for (int jj = 0; jj < 2; jj++) {
                uint32_t tmp[4];
                const int krow = ksb * 16 + b_krlo;
                const int nch = b_ncsel + jj * 2;
                ldsm_x4_t(tmp, bb + (uint32_t)(krow * 256) + (uint32_t)((nch ^ (krow & 7)) << 4));
                bf[jj * 2][0] = tmp[0]; bf[jj * 2][1] = tmp[1];
                bf[jj * 2 + 1][0] = tmp[2]; bf[jj * 2 + 1][1] = tmp[3];
            }
#pragma unroll
            for (int i = 0; i < 4; i++)
#pragma unroll
                for (int j = 0; j < 4; j++)
                    mma_f16(acc[i][j], av[i], bf[j]);
        }
    }

#pragma unroll
    for (int i = 0; i < 4; i++) {
        const int r0 = bm + wm * 64 + i * 16 + (lane >> 2);
#pragma unroll
        for (int j = 0; j < 4; j++) {
            const int col = bn + wn * 32 + j * 8 + (lane & 3) * 2;
            float2 bi = *(const float2*)(bias + col);
            float o00 = acc[i][j][0] + bi.x;
            float o01 = acc[i][j][1] + bi.y;
            float o10 = acc[i][j][2] + bi.x;
            float o11 = acc[i][j][3] + bi.y;
            if (EPI == 1) {
                o00 = fmaxf(o00, 0.f); o01 = fmaxf(o01, 0.f);
                o10 = fmaxf(o10, 0.f); o11 = fmaxf(o11, 0.f);
            }
            if (EPI == 2) {
                float2 r0v = *(const float2*)(res + (size_t)r0 * N + col);
                float2 r1v = *(const float2*)(res + (size_t)(r0 + 8) * N + col);
                o00 += r0v.x; o01 += r0v.y;
                o10 += r1v.x; o11 += r1v.y;
            }
            if (HOUT) {
                __half* Ch = (__half*)Cv;
                *(__half2*)(Ch + (size_t)r0 * N + col) = __floats2half2_rn(o00, o01);
                *(__half2*)(Ch + (size_t)(r0 + 8) * N + col) = __floats2half2_rn(o10, o11);
            } else {
                float* Cf = (float*)Cv;
                *(float2*)(Cf + (size_t)r0 * N + col) = make_float2(o00, o01);
                *(float2*)(Cf + (size_t)(r0 + 8) * N + col) = make_float2(o10, o11);
            }
        }
    }
}

template <int EPI, bool HOUT>
__global__ __launch_bounds__(256, 2) void hgemm_kernel(
    const __half* __restrict__ A, const __half* __restrict__ W,
    const float* __restrict__ bias, const float* __restrict__ res,
    void* __restrict__ C, int M, int N, int K)
{
    hgemm_body<EPI, HOUT>(A, W, bias, res, C, M, N, K);
}

// ---------------------------------------------------------------------------
// fp16 flash attention (round-13 validated, unchanged)
// ---------------------------------------------------------------------------
#define FBK 64
#define KROW 72
#define KBUF (64 * KROW)
#define NSTAGE 3
#define FLASH_SMEM_BYTES (NSTAGE * 2 * KBUF * 2)

__global__ __launch_bounds__(256, 2) void flash_fp16_kernel(
    const __half* __restrict__ qkv, const unsigned char* __restrict__ mask,
    __half* __restrict__ ctxh)
{
    extern __shared__ __half fh[];
    const uint32_t ks_u = smem_u32(fh);
    const uint32_t vs_u = ks_u + NSTAGE * KBUF * 2;

    const int tid = threadIdx.x;
    const int lane = tid & 31;
    const int warp = tid >> 5;
    const int bh = blockIdx.y;
    const int b = bh >> 4;
    const int h = bh & 15;
    const int q0 = blockIdx.x * 128;
    const int hoff = h * DH_;
    const unsigned char* mrow = mask + (size_t)b * S_;

    const int r0 = lane >> 2;
    const int c0 = lane & 3;
    const int lrow = lane & 15;
    const int lhi = lane >> 4;

    uint32_t qf[4][4];
    {
        const size_t rowa = (size_t)(b * S_ + q0 + warp * 16 + r0) * QKS + hoff;
#pragma unroll
        for (int ks = 0; ks < 4; ks++) {
            const int c = ks * 16 + 2 * c0;
            qf[ks][0] = *(const uint32_t*)(qkv + rowa + c);
            qf[ks][1] = *(const uint32_t*)(qkv + rowa + (size_t)8 * QKS + c);
            qf[ks][2] = *(const uint32_t*)(qkv + rowa + c + 8);
            qf[ks][3] = *(const uint32_t*)(qkv + rowa + (size_t)8 * QKS + c + 8);
        }
    }

    float oa[8][4];
    float mx0 = -1e30f, mx1 = -1e30f, l0 = 0.f, l1 = 0.f;
#pragma unroll
    for (int j = 0; j < 8; j++)
#pragma unroll
        for (int r = 0; r < 4; r++) oa[j][r] = 0.f;

    const int id0 = tid, id1 = tid + 256;
    const int krow0 = id0 >> 3, kch0 = id0 & 7;
    const int krow1 = id1 >> 3, kch1 = id1 & 7;

    const __half* kbase = qkv + (size_t)b * S_ * QKS + 1024 + hoff;
    const __half* vbase = qkv + (size_t)b * S_ * QKS + 2048 + hoff;

    const int NT = S_ / FBK;

    auto issue = [&](int st, int kt) {
        const uint32_t kdst = ks_u + (uint32_t)(st * KBUF) * 2;
        const uint32_t vdst = vs_u + (uint32_t)(st * KBUF) * 2;
        cpasync16(kdst + (uint32_t)(krow0 * KROW) * 2 + kch0 * 16,
                  kbase + (size_t)(kt + krow0) * QKS + kch0 * 8);
        cpasync16(kdst + (uint32_t)(krow1 * KROW) * 2 + kch1 * 16,
                  kbase + (size_t)(kt + krow1) * QKS + kch1 * 8);
        cpasync16(vdst + (uint32_t)(krow0 * KROW) * 2 + kch0 * 16,
                  vbase + (size_t)(kt + krow0) * QKS + kch0 * 8);
        cpasync16(vdst + (uint32_t)(krow1 * KROW) * 2 + kch1 * 16,
                  vbase + (size_t)(kt + krow1) * QKS + kch1 * 8);
        cpasync_commit();
    };

    issue(0, 0);
    issue(1, FBK);

    for (int t = 0; t < NT; t++) {
        const int kt = t * FBK;
        if (t + 1 < NT) cpasync_wait<1>();
        else cpasync_wait<0>();
        __syncthreads();
        if (t + 2 < NT) issue((t + 2) % NSTAGE, kt + 2 * FBK);

        const uint32_t kc_u = ks_u + (uint32_t)((t % NSTAGE) * KBUF) * 2;
        const uint32_t vc_u = vs_u + (uint32_t)((t % NSTAGE) * KBUF) * 2;

        float sa[8][4];
#pragma unroll
        for (int j = 0; j < 8; j++)
#pragma unroll
            for (int r = 0; r < 4; r++) sa[j][r] = 0.f;

#pragma unroll
        for (int ks = 0; ks < 4; ks++) {
#pragma unroll
            for (int jp = 0; jp < 4; jp++) {
                uint32_t kv4[4];
                ldsm_x4(kv4, kc_u + (uint32_t)(((jp * 16 + lrow) * KROW + ks * 16 + lhi * 8) * 2));
                uint32_t b0[2] = {kv4[0], kv4[2]};
                uint32_t b1[2] = {kv4[1], kv4[3]};
                mma_f16(sa[2 * jp], qf[ks], b0);
                mma_f16(sa[2 * jp + 1], qf[ks], b1);
            }
        }

        float rm0 = -1e30f, rm1 = -1e30f;
#pragma unroll
        for (int j = 0; j < 8; j++) {
            const int col = kt + j * 8 + 2 * c0;
            const bool m0 = mrow[col] != 0;
            const bool m1 = mrow[col + 1] != 0;
            sa[j][0] = m0 ? -1e9f : sa[j][0] * 0.125f;
            sa[j][1] = m1 ? -1e9f : sa[j][1] * 0.125f;
            sa[j][2] = m0 ? -1e9f : sa[j][2] * 0.125f;
            sa[j][3] = m1 ? -1e9f : sa[j][3] * 0.125f;
            rm0 = fmaxf(rm0, fmaxf(sa[j][0], sa[j][1]));
            rm1 = fmaxf(rm1, fmaxf(sa[j][2], sa[j][3]));
        }
        rm0 = fmaxf(rm0, __shfl_xor_sync(0xffffffffu, rm0, 1));
        rm0 = fmaxf(rm0, __shfl_xor_sync(0xffffffffu, rm0, 2));
        rm1 = fmaxf(rm1, __shfl_xor_sync(0xffffffffu, rm1, 1));
        rm1 = fmaxf(rm1, __shfl_xor_sync(0xffffffffu, rm1, 2));

        const float mn0 = fmaxf(mx0, rm0);
        const float mn1 = fmaxf(mx1, rm1);
        const float corr0 = __expf(mx0 - mn0);
        const float corr1 = __expf(mx1 - mn1);
        mx0 = mn0; mx1 = mn1;

        float rs0 = 0.f, rs1 = 0.f;
#pragma unroll
        for (int j = 0; j < 8; j++) {
            sa[j][0] = __expf(sa[j][0] - mn0);
            sa[j][1] = __expf(sa[j][1] - mn0);
            sa[j][2] = __expf(sa[j][2] - mn1);
            sa[j][3] = __expf(sa[j][3] - mn1);
            rs0 += sa[j][0] + sa[j][1];
            rs1 += sa[j][2] + sa[j][3];
            oa[j][0] *= corr0; oa[j][1] *= corr0;
            oa[j][2] *= corr1; oa[j][3] *= corr1;
        }
        rs0 += __shfl_xor_sync(0xffffffffu, rs0, 1);
        rs0 += __shfl_xor_sync(0xffffffffu, rs0, 2);
        rs1 += __shfl_xor_sync(0xffffffffu, rs1, 1);
        rs1 += __shfl_xor_sync(0xffffffffu, rs1, 2);
        l0 = l0 * corr0 + rs0;
        l1 = l1 * corr1 + rs1;

#pragma unroll
        for (int ks = 0; ks < 4; ks++) {
            uint32_t pf[4];
            pf[0] = h2u(__floats2half2_rn(sa[2 * ks][0], sa[2 * ks][1]));
            pf[1] = h2u(__floats2half2_rn(sa[2 * ks][2], sa[2 * ks][3]));
            pf[2] = h2u(__floats2half2_rn(sa[2 * ks + 1][0], sa[2 * ks + 1][1]));
            pf[3] = h2u(__floats2half2_rn(sa[2 * ks + 1][2], sa[2 * ks + 1][3]));
#pragma unroll
            for (int q = 0; q < 4; q++) {
                uint32_t t4[4];
                ldsm_x4_t(t4, vc_u + (uint32_t)(((ks * 16 + lrow) * KROW + (2 * q + lhi) * 8) * 2));
                mma_f16(oa[2 * q], pf, t4);
                mma_f16(oa[2 * q + 1], pf, t4 + 2);
            }
        }
    }

    const float inv0 = 1.f / l0;
    const float inv1 = 1.f / l1;
    const int row0 = q0 + warp * 16 + r0;
    const size_t obase = (size_t)b * S_ * D_ + hoff;
#pragma unroll
    for (int j = 0; j < 8; j++) {
        const int col = j * 8 + 2 * c0;
        *(__half2*)(ctxh + obase + (size_t)row0 * D_ + col) =
            __floats2half2_rn(oa[j][0] * inv0, oa[j][1] * inv0);
        *(__half2*)(ctxh + obase + (size_t)(row0 + 8) * D_ + col) =
            __floats2half2_rn(oa[j][2] * inv1, oa[j][3] * inv1);
    }
}

// ---------------------------------------------------------------------------
// LayerNorm
// ---------------------------------------------------------------------------
__global__ __launch_bounds__(256) void ln_kernel(
    const float* __restrict__ in, const float* __restrict__ g,
    const float* __restrict__ be, float* __restrict__ out,
    __half* __restrict__ outh)
{
    __shared__ float sred[8], ssred[8];
    __shared__ float muSh, rsSh;

    const int row = blockIdx.x;
    const int tid = threadIdx.x;
    const int lane = tid & 31;
    const int wid = tid >> 5;

    const float* p = in + (size_t)row * D_;
    float4 x = *(const float4*)(p + tid * 4);
    float s = x.x + x.y + x.z + x.w;
    float ss = x.x * x.x + x.y * x.y + x.z * x.z + x.w * x.w;

#pragma unroll
    for (int off = 16; off > 0; off >>= 1) {
        s += __shfl_xor_sync(0xffffffffu, s, off);
        ss += __shfl_xor_sync(0xffffffffu, ss, off);
    }
    if (lane == 0) { sred[wid] = s; ssred[wid] = ss; }
    __syncthreads();
    if (wid == 0) {
        float s2 = (lane < 8) ? sred[lane] : 0.f;
        float ss2 = (lane < 8) ? ssred[lane] : 0.f;
#pragma unroll
        for (int off = 4; off > 0; off >>= 1) {
            s2 += __shfl_xor_sync(0xffffffffu, s2, off);
            ss2 += __shfl_xor_sync(0xffffffffu, ss2, off);
        }
        if (lane == 0) {
            const float mu = s2 * (1.f / D_);
            const float var = ss2 * (1.f / D_) - mu * mu;
            muSh = mu;
            rsSh = rsqrtf(var + 1e-6f);
        }
    }
    __syncthreads();

    const float mu = muSh, rs = rsSh;
    float4 gg = *(const float4*)(g + tid * 4);
    float4 bb = *(const float4*)(be + tid * 4);
    float4 y;
    y.x = (x.x - mu) * rs * gg.x + bb.x;
    y.y = (x.y - mu) * rs * gg.y + bb.y;
    y.z = (x.z - mu) * rs * gg.z + bb.z;
    y.w = (x.w - mu) * rs * gg.w + bb.w;
    *(float4*)(out + (size_t)row * D_ + tid * 4) = y;
    if (outh) {
        *(__half2*)(outh + (size_t)row * D_ + tid * 4)     = __floats2half2_rn(y.x, y.y);
        *(__half2*)(outh + (size_t)row * D_ + tid * 4 + 2) = __floats2half2_rn(y.z, y.w);
    }
}

// ---------------------------------------------------------------------------
// Launch
// ---------------------------------------------------------------------------
extern "C" void kernel_launch(void* const* d_in, const int* in_sizes, int n_in,
                              void* d_out, int out_size)
{
    const float* x   = (const float*)d_in[0];
    const unsigned char* mask = (const unsigned char*)d_in[1];
    const float* wq = (const float*)d_in[2];
    const float* bq = (const float*)d_in[3];
    const float* wk = (const float*)d_in[4];
    const float* bk = (const float*)d_in[5];
    const float* wv = (const float*)d_in[6];
    const float* bv = (const float*)d_in[7];
    const float* wm = (const float*)d_in[8];
    const float* bm = (const float*)d_in[9];
    const float* w1 = (const float*)d_in[10];
    const float* b1 = (const float*)d_in[11];
    const float* w2 = (const float*)d_in[12];
    const float* b2 = (const float*)d_in[13];
    const float* g1  = (const float*)d_in[14];
    const float* be1 = (const float*)d_in[15];
    const float* g2  = (const float*)d_in[16];
    const float* be2 = (const float*)d_in[17];
    float* out = (float*)d_out;

    float *y1, *x1, *bqkv;
    __half *xh, *whqkv, *wh, *qkvh, *ctxh, *x1h, *hbh;
    cudaGetSymbolAddress((void**)&y1, g_y1);
    cudaGetSymbolAddress((void**)&x1, g_x1);
    cudaGetSymbolAddress((void**)&bqkv, g_bqkv);
    cudaGetSymbolAddress((void**)&xh, g_xh);
    cudaGetSymbolAddress((void**)&whqkv, g_whqkv);
    cudaGetSymbolAddress((void**)&wh, g_wh);
    cudaGetSymbolAddress((void**)&qkvh, g_qkvh);
    cudaGetSymbolAddress((void**)&ctxh, g_ctxh);
    cudaGetSymbolAddress((void**)&x1h, g_x1h);
    cudaGetSymbolAddress((void**)&hbh, g_hbh);

    __half* whm = wh;
    __half* wh1 = wh + (size_t)1 * 1024 * 1024;
    __half* wh2 = wh + (size_t)5 * 1024 * 1024;

    cudaFuncSetAttribute(hgemm_kernel<0, true>,  cudaFuncAttributeMaxDynamicSharedMemorySize, GEMM_SMEM_BYTES);
    cudaFuncSetAttribute(hgemm_kernel<1, true>,  cudaFuncAttributeMaxDynamicSharedMemorySize, GEMM_SMEM_BYTES);
    cudaFuncSetAttribute(hgemm_kernel<2, false>, cudaFuncAttributeMaxDynamicSharedMemorySize, GEMM_SMEM_BYTES);
    cudaFuncSetAttribute(flash_fp16_kernel, cudaFuncAttributeMaxDynamicSharedMemorySize, FLASH_SMEM_BYTES);

    // side stream + fork/join events (created once; no device memory involved)
    static cudaStream_t s1 = nullptr;
    static cudaEvent_t ev_fork = nullptr, ev_join = nullptr;
    if (s1 == nullptr) {
        cudaStreamCreateWithFlags(&s1, cudaStreamNonBlocking);
        cudaEventCreateWithFlags(&ev_fork, cudaEventDisableTiming);
        cudaEventCreateWithFlags(&ev_join, cudaEventDisableTiming);
    }

    const dim3 blk(256);

    // Fused pre-pass on main stream (x convert + qkv weight pack + bias)
    prep_main_kernel<<<11267, blk>>>(x, xh, wq, wk, wv, whqkv, bq, bk, bv, bqkv);

    // Fork: wm/w1/w2 conversion overlaps QKV GEMM + flash
    cudaEventRecord(ev_fork, 0);
    cudaStreamWaitEvent(s1, ev_fork, 0);
    prep_rest_kernel<<<9216, blk, 0, s1>>>(wm, w1, w2, whm, wh1, wh2);
    cudaEventRecord(ev_join, s1);

    // Packed QKV GEMM
    hgemm_kernel<0, true><<<dim3(QKS / 128, NTOK / 128), blk, GEMM_SMEM_BYTES>>>(
        xh, whqkv, bqkv, nullptr, qkvh, NTOK, QKS, D_);

    // Flash attention -> ctxh
    flash_fp16_kernel<<<dim3(S_ / 128, B_ * H_), blk, FLASH_SMEM_BYTES>>>(qkvh, mask, ctxh);

    // Join: converted wm/w1/w2 needed from here on
    cudaStreamWaitEvent(0, ev_join, 0);

    // proj + residual -> y1 (fp32)
    hgemm_kernel<2, false><<<dim3(D_ / 128, NTOK / 128), blk, GEMM_SMEM_BYTES>>>(
        ctxh, whm, bm, x, y1, NTOK, D_, D_);
    ln_kernel<<<NTOK, blk>>>(y1, g1, be1, x1, x1h);

    // FFN
    hgemm_kernel<1, true><<<dim3(FF_ / 128, NTOK / 128), blk, GEMM_SMEM_BYTES>>>(
        x1h, wh1, b1, nullptr, hbh, NTOK, FF_, D_);
    hgemm_kernel<2, false><<<dim3(D_ / 128, NTOK / 128), blk, GEMM_SMEM_BYTES>>>(
        hbh, wh2, b2, x1, y1, NTOK, D_, FF_);
    ln_kernel<<<NTOK, blk>>>(y1, g2, be2, out, nullptr);
}

// round 17
// speedup vs baseline: 1.1091x; 1.0175x over previous
#include <cuda_runtime.h>
#include <cuda_fp16.h>
#include <math.h>
#include <stdint.h>

// Problem constants
#define B_   4
#define S_   2048
#define D_   1024
#define H_   16
#define DH_  64
#define FF_  4096
#define NTOK (B_ * S_)   // 8192
#define QKS  3072        // packed qkv row stride

// ---------------------------------------------------------------------------
// Scratch buffers
// ---------------------------------------------------------------------------
__device__ float  g_y1[(size_t)NTOK * D_];
__device__ float  g_x1[(size_t)NTOK * D_];
__device__ float  g_bqkv[QKS];
__device__ float  g_mb[(size_t)B_ * S_];            // mask bias (0 / -1e9)
__device__ __half g_xh[(size_t)NTOK * D_];
__device__ __half g_whqkv[(size_t)D_ * QKS];
__device__ __half g_wh[(size_t)9 * 1024 * 1024];    // wm (1M), w1 (4M), w2 (4M)
__device__ __half g_qkvh[(size_t)NTOK * QKS];       // packed q|k|v fp16
__device__ __half g_ctxh[(size_t)NTOK * D_];
__device__ __half g_x1h[(size_t)NTOK * D_];
__device__ __half g_hbh[(size_t)NTOK * FF_];

// ---------------------------------------------------------------------------
// helpers
// ---------------------------------------------------------------------------
__device__ __forceinline__ void mma_f16(float* d, const uint32_t* a, const uint32_t* b) {
    asm volatile(
        "mma.sync.aligned.m16n8k16.row.col.f32.f16.f16.f32 "
        "{%0,%1,%2,%3}, {%4,%5,%6,%7}, {%8,%9}, {%0,%1,%2,%3};"
        : "+f"(d[0]), "+f"(d[1]), "+f"(d[2]), "+f"(d[3])
        : "r"(a[0]), "r"(a[1]), "r"(a[2]), "r"(a[3]), "r"(b[0]), "r"(b[1]));
}

__device__ __forceinline__ uint32_t smem_u32(const void* p) {
    uint32_t a;
    asm("{ .reg .u64 t; cvta.to.shared.u64 t, %1; cvt.u32.u64 %0, t; }" : "=r"(a) : "l"(p));
    return a;
}

__device__ __forceinline__ void cpasync16(uint32_t dst, const void* src) {
    asm volatile("cp.async.cg.shared.global [%0], [%1], 16;" :: "r"(dst), "l"(src) : "memory");
}
__device__ __forceinline__ void cpasync_commit() {
    asm volatile("cp.async.commit_group;" ::: "memory");
}
template <int N>
__device__ __forceinline__ void cpasync_wait() {
    asm volatile("cp.async.wait_group %0;" :: "n"(N) : "memory");
}

__device__ __forceinline__ void ldsm_x4(uint32_t* r, uint32_t addr) {
    asm volatile("ldmatrix.sync.aligned.m8n8.x4.shared.b16 {%0,%1,%2,%3}, [%4];"
                 : "=r"(r[0]), "=r"(r[1]), "=r"(r[2]), "=r"(r[3]) : "r"(addr));
}
__device__ __forceinline__ void ldsm_x4_t(uint32_t* r, uint32_t addr) {
    asm volatile("ldmatrix.sync.aligned.m8n8.x4.trans.shared.b16 {%0,%1,%2,%3}, [%4];"
                 : "=r"(r[0]), "=r"(r[1]), "=r"(r[2]), "=r"(r[3]) : "r"(addr));
}

__device__ __forceinline__ uint32_t h2u(__half2 h) {
    return *reinterpret_cast<uint32_t*>(&h);
}

// ---------------------------------------------------------------------------
// Pre-pass kernels
// prep_main: [0,8192): f2h(x); [8192,11264): qkv weight pack;
//            [11264,11267): bias pack; [11267,11275): mask -> fp32 bias.
// prep_rest: wm/w1/w2 conversion (runs on side stream).
// ---------------------------------------------------------------------------
__global__ __launch_bounds__(256) void prep_main_kernel(
    const float* __restrict__ x, __half* __restrict__ xh,
    const float* __restrict__ wq, const float* __restrict__ wk,
    const float* __restrict__ wv, __half* __restrict__ whqkv,
    const float* __restrict__ bq, const float* __restrict__ bk,
    const float* __restrict__ bv, float* __restrict__ bqkv,
    const unsigned char* __restrict__ mask, float* __restrict__ mb)
{
    const int bid = blockIdx.x;
    if (bid < 8192) {
        const int i = (bid * 256 + threadIdx.x) * 4;
        float4 v = *(const float4*)(x + i);
        *(__half2*)(xh + i)     = __floats2half2_rn(v.x, v.y);
        *(__half2*)(xh + i + 2) = __floats2half2_rn(v.z, v.w);
    } else if (bid < 11264) {
        const int pb = bid - 8192;
        const int y = pb >> 10;
        const int i = ((pb & 1023) * 256 + threadIdx.x) * 4;
        const float* src = (y == 0) ? wq : (y == 1) ? wk : wv;
        float4 v = *(const float4*)(src + i);
        __half* o = whqkv + (size_t)(i >> 10) * QKS + y * 1024 + (i & 1023);
        *(__half2*)o       = __floats2half2_rn(v.x, v.y);
        *(__half2*)(o + 2) = __floats2half2_rn(v.z, v.w);
    } else if (bid < 11267) {
        const int i = (bid - 11264) * 256 + threadIdx.x;
#pragma unroll
        for (int r = 0; r < 4; r++) {
            const int j = i * 4 + r;
            bqkv[j] = (j < 1024) ? bq[j] : (j < 2048) ? bk[j - 1024] : bv[j - 2048];
        }
    } else {
        const int i = ((bid - 11267) * 256 + threadIdx.x) * 4;  // 8 blocks -> 8192
#pragma unroll
        for (int r = 0; r < 4; r++)
            mb[i + r] = (mask[i + r] != 0) ? -1e9f : 0.f;
    }
}

__global__ __launch_bounds__(256) void prep_rest_kernel(
    const float* __restrict__ wm, const float* __restrict__ w1,
    const float* __restrict__ w2, __half* __restrict__ whm,
    __half* __restrict__ wh1, __half* __restrict__ wh2)
{
    const int bid = blockIdx.x;
    const float* src;
    __half* dst;
    int i;
    if (bid < 1024) { src = wm; dst = whm; i = (bid * 256 + threadIdx.x) * 4; }
    else if (bid < 5120) { src = w1; dst = wh1; i = ((bid - 1024) * 256 + threadIdx.x) * 4; }
    else { src = w2; dst = wh2; i = ((bid - 5120) * 256 + threadIdx.x) * 4; }
    float4 v = *(const float4*)(src + i);
    *(__half2*)(dst + i)     = __floats2half2_rn(v.x, v.y);
    *(__half2*)(dst + i + 2) = __floats2half2_rn(v.z, v.w);
}

// ---------------------------------------------------------------------------
// fp16 GEMM (round-13 validated): GK=32, 4-stage cp.async + ldmatrix,
// 2 CTA/SM, one sync per iteration.
// ---------------------------------------------------------------------------
#define GK 32
#define ASTG (128 * 32)
#define BSTG (32 * 128)
#define STGH (ASTG + BSTG)
#define NSTG 4
#define GEMM_SMEM_BYTES (NSTG * STGH * 2)   // 65536

template <int EPI, bool HOUT>
__device__ __forceinline__ void hgemm_body(
    const __half* __restrict__ A, const __half* __restrict__ W,
    const float* __restrict__ bias, const float* __restrict__ res,
    void* __restrict__ Cv, int M, int N, int K)
{
    extern __shared__ __half hsm[];
    const uint32_t sbase = smem_u32(hsm);

    const int tid = threadIdx.x;
    const int lane = tid & 31;
    const int warp = tid >> 5;
    const int wm = warp >> 2;
    const int wn = warp & 3;
    const int bm = blockIdx.y * 128;
    const int bn = blockIdx.x * 128;

    const int ar0 = tid >> 2;
    const int akc = tid & 3;
    const int bkr = tid >> 4;
    const int bnc = tid & 15;

    const __half* Ag = A + (size_t)bm * K;
    const __half* Wg = W + bn;

    const uint32_t a_off1 = (uint32_t)(ar0 * 64 + ((akc ^ ((ar0 >> 1) & 3)) << 4));
    const uint32_t a_off2 = (uint32_t)((ar0 + 64) * 64 + ((akc ^ (((ar0 + 64) >> 1) & 3)) << 4));
    const uint32_t b_off1 = (uint32_t)(bkr * 256 + ((bnc ^ (bkr & 7)) << 4));
    const uint32_t b_off2 = (uint32_t)((bkr + 16) * 256 + ((bnc ^ ((bkr + 16) & 7)) << 4));

    uint32_t a_row_off[4];
    int a_row_sw[4];
#pragma unroll
    for (int i = 0; i < 4; i++) {
        const int row = wm * 64 + i * 16 + (lane & 15);
        a_row_off[i] = (uint32_t)(row * 64);
        a_row_sw[i] = (row >> 1) & 3;
    }
    const int a_csel = lane >> 4;
    const int b_krlo = lane & 15;
    const int b_ncsel = wn * 4 + (lane >> 4);

    float acc[4][4][4];
#pragma unroll
    for (int i = 0; i < 4; i++)
#pragma unroll
        for (int j = 0; j < 4; j++)
#pragma unroll
            for (int r = 0; r < 4; r++) acc[i][j][r] = 0.f;

    const int NIT = K / GK;

    auto issue = [&](int s, int k0) {
        const uint32_t ab = sbase + (uint32_t)(s * STGH) * 2;
        const uint32_t bb = ab + ASTG * 2;
        cpasync16(ab + a_off1, Ag + (size_t)ar0 * K + k0 + akc * 8);
        cpasync16(ab + a_off2, Ag + (size_t)(ar0 + 64) * K + k0 + akc * 8);
        cpasync16(bb + b_off1, Wg + (size_t)(k0 + bkr) * N + bnc * 8);
        cpasync16(bb + b_off2, Wg + (size_t)(k0 + bkr + 16) * N + bnc * 8);
        cpasync_commit();
    };

    issue(0, 0);
    issue(1, GK);
    issue(2, 2 * GK);

    for (int t = 0; t < NIT; t++) {
        if (t + 2 < NIT) cpasync_wait<2>();
        else if (t + 1 < NIT) cpasync_wait<1>();
        else cpasync_wait<0>();
        __syncthreads();
        if (t + 3 < NIT) issue((t + 3) & 3, (t + 3) * GK);

        const uint32_t ab = sbase + (uint32_t)((t & 3) * STGH) * 2;
        const uint32_t bb = ab + ASTG * 2;

#pragma unroll
        for (int ksb = 0; ksb < 2; ksb++) {
            uint32_t av[4][4];
#pragma unroll
            for (int i = 0; i < 4; i++) {
                const int lch = ksb * 2 + a_csel;
                ldsm_x4(av[i], ab + a_row_off[i] + (uint32_t)((lch ^ a_row_sw[i]) << 4));
            }
            uint32_t bf[4][2];
#pragma unroll
            for (int jj = 0; jj < 2; jj++) {
                uint32_t tmp[4];
                const int krow = ksb * 16 + b_krlo;
                const int nch = b_ncsel + jj * 2;
                ldsm_x4_t(tmp, bb + (uint32_t)(krow * 256) + (uint32_t)((nch ^ (krow & 7)) << 4));
                bf[jj * 2][0] = tmp[0]; bf[jj * 2][1] = tmp[1];
                bf[jj * 2 + 1][0] = tmp[2]; bf[jj * 2 + 1][1] = tmp[3];
            }
#pragma unroll
            for (int i = 0; i < 4; i++)
#pragma unroll
                for (int j = 0; j < 4; j++)
                    mma_f16(acc[i][j], av[i], bf[j]);
        }
    }

#pragma unroll
    for (int i = 0; i < 4; i++) {
        const int r0 = bm + wm * 64 + i * 16 + (lane >> 2);
#pragma unroll
        for (int j = 0; j < 4; j++) {
            const int col = bn + wn * 32 + j * 8 + (lane & 3) * 2;
            float2 bi = *(const float2*)(bias + col);
            float o00 = acc[i][j][0] + bi.x;
            float o01 = acc[i][j][1] + bi.y;
            float o10 = acc[i][j][2] + bi.x;
            float o11 = acc[i][j][3] + bi.y;
            if (EPI == 1) {
                o00 = fmaxf(o00, 0.f); o01 = fmaxf(o01, 0.f);
                o10 = fmaxf(o10, 0.f); o11 = fmaxf(o11, 0.f);
            }
            if (EPI == 2) {
                float2 r0v = *(const float2*)(res + (size_t)r0 * N + col);
                float2 r1v = *(const float2*)(res + (size_t)(r0 + 8) * N + col);
                o00 += r0v.x; o01 += r0v.y;
                o10 += r1v.x; o11 += r1v.y;
            }
            if (HOUT) {
                __half* Ch = (__half*)Cv;
                *(__half2*)(Ch + (size_t)r0 * N + col) = __floats2half2_rn(o00, o01);
                *(__half2*)(Ch + (size_t)(r0 + 8) * N + col) = __floats2half2_rn(o10, o11);
            } else {
                float* Cf = (float*)Cv;
                *(float2*)(Cf + (size_t)r0 * N + col) = make_float2(o00, o01);
                *(float2*)(Cf + (size_t)(r0 + 8) * N + col) = make_float2(o10, o11);
            }
        }
    }
}

template <int EPI, bool HOUT>
__global__ __launch_bounds__(256, 2) void hgemm_kernel(
    const __half* __restrict__ A, const __half* __restrict__ W,
    const float* __restrict__ bias, const float* __restrict__ res,
    void* __restrict__ C, int M, int N, int K)
{
    hgemm_body<EPI, HOUT>(A, W, bias, res, C, M, N, K);
}

// ---------------------------------------------------------------------------
// fp16 flash attention. Q pre-scaled by 0.125 (exact); mask via fp32 bias.
// ---------------------------------------------------------------------------
#define FBK 64
#define KROW 72
#define KBUF (64 * KROW)
#define NSTAGE 3
#define FLASH_SMEM_BYTES (NSTAGE * 2 * KBUF * 2)

__global__ __launch_bounds__(256, 2) void flash_fp16_kernel(
    const __half* __restrict__ qkv, const float* __restrict__ mb,
    __half* __restrict__ ctxh)
{
    extern __shared__ __half fh[];
    const uint32_t ks_u = smem_u32(fh);
    const uint32_t vs_u = ks_u + NSTAGE * KBUF * 2;

    const int tid = threadIdx.x;
    const int lane = tid & 31;
    const int warp = tid >> 5;
    const int bh = blockIdx.y;
    const int b = bh >> 4;
    const int h = bh & 15;
    const int q0 = blockIdx.x * 128;
    const int hoff = h * DH_;
    const float* mrow = mb + (size_t)b * S_;

    const int r0 = lane >> 2;
    const int c0 = lane & 3;
    const int lrow = lane & 15;
    const int lhi = lane >> 4;

    // Q A-frags, pre-scaled by 0.125 (exponent shift, exact in fp16)
    uint32_t qf[4][4];
    {
        const __half2 sc = __float2half2_rn(0.125f);
        const size_t rowa = (size_t)(b * S_ + q0 + warp * 16 + r0) * QKS + hoff;
#pragma unroll
        for (int ks = 0; ks < 4; ks++) {
            const int c = ks * 16 + 2 * c0;
            qf[ks][0] = *(const uint32_t*)(qkv + rowa + c);
            qf[ks][1] = *(const uint32_t*)(qkv + rowa + (size_t)8 * QKS + c);
            qf[ks][2] = *(const uint32_t*)(qkv + rowa + c + 8);
            qf[ks][3] = *(const uint32_t*)(qkv + rowa + (size_t)8 * QKS + c + 8);
#pragma unroll
            for (int r = 0; r < 4; r++)
                qf[ks][r] = h2u(__hmul2(*(__half2*)&qf[ks][r], sc));
        }
    }

    float oa[8][4];
    float mx0 = -1e30f, mx1 = -1e30f, l0 = 0.f, l1 = 0.f;
#pragma unroll
    for (int j = 0; j < 8; j++)
#pragma unroll
        for (int r = 0; r < 4; r++) oa[j][r] = 0.f;

    const int id0 = tid, id1 = tid + 256;
    const int krow0 = id0 >> 3, kch0 = id0 & 7;
    const int krow1 = id1 >> 3, kch1 = id1 & 7;

    const __half* kbase = qkv + (size_t)b * S_ * QKS + 1024 + hoff;
    const __half* vbase = qkv + (size_t)b * S_ * QKS + 2048 + hoff;

    const int NT = S_ / FBK;

    auto issue = [&](int st, int kt) {
        const uint32_t kdst = ks_u + (uint32_t)(st * KBUF) * 2;
        const uint32_t vdst = vs_u + (uint32_t)(st * KBUF) * 2;
        cpasync16(kdst + (uint32_t)(krow0 * KROW) * 2 + kch0 * 16,
                  kbase + (size_t)(kt + krow0) * QKS + kch0 * 8);
        cpasync16(kdst + (uint32_t)(krow1 * KROW) * 2 + kch1 * 16,
                  kbase + (size_t)(kt + krow1) * QKS + kch1 * 8);
        cpasync16(vdst + (uint32_t)(krow0 * KROW) * 2 + kch0 * 16,
                  vbase + (size_t)(kt + krow0) * QKS + kch0 * 8);
        cpasync16(vdst + (uint32_t)(krow1 * KROW) * 2 + kch1 * 16,
                  vbase + (size_t)(kt + krow1) * QKS + kch1 * 8);
        cpasync_commit();
    };

    issue(0, 0);
    issue(1, FBK);

    for (int t = 0; t < NT; t++) {
        const int kt = t * FBK;
        if (t + 1 < NT) cpasync_wait<1>();
        else cpasync_wait<0>();
        __syncthreads();
        if (t + 2 < NT) issue((t + 2) % NSTAGE, kt + 2 * FBK);

        const uint32_t kc_u = ks_u + (uint32_t)((t % NSTAGE) * KBUF) * 2;
        const uint32_t vc_u = vs_u + (uint32_t)((t % NSTAGE) * KBUF) * 2;

        // ---- S = (Q/8) @ K^T ----
        float sa[8][4];
#pragma unroll
        for (int j = 0; j < 8; j++)
#pragma unroll
            for (int r = 0; r < 4; r++) sa[j][r] = 0.f;

#pragma unroll
        for (int ks = 0; ks < 4; ks++) {
#pragma unroll
            for (int jp = 0; jp < 4; jp++) {
                uint32_t kv4[4];
                ldsm_x4(kv4, kc_u + (uint32_t)(((jp * 16 + lrow) * KROW + ks * 16 + lhi * 8) * 2));
                uint32_t b0[2] = {kv4[0], kv4[2]};
                uint32_t b1[2] = {kv4[1], kv4[3]};
                mma_f16(sa[2 * jp], qf[ks], b0);
                mma_f16(sa[2 * jp + 1], qf[ks], b1);
            }
        }

        // ---- mask bias + row max ----
        float rm0 = -1e30f, rm1 = -1e30f;
#pragma unroll
        for (int j = 0; j < 8; j++) {
            float2 mbv = *(const float2*)(mrow + kt + j * 8 + 2 * c0);
            sa[j][0] += mbv.x;
            sa[j][1] += mbv.y;
            sa[j][2] += mbv.x;
            sa[j][3] += mbv.y;
            rm0 = fmaxf(rm0, fmaxf(sa[j][0], sa[j][1]));
            rm1 = fmaxf(rm1, fmaxf(sa[j][2], sa[j][3]));
        }
        rm0 = fmaxf(rm0, __shfl_xor_sync(0xffffffffu, rm0, 1));
        rm0 = fmaxf(rm0, __shfl_xor_sync(0xffffffffu, rm0, 2));
        rm1 = fmaxf(rm1, __shfl_xor_sync(0xffffffffu, rm1, 1));
        rm1 = fmaxf(rm1, __shfl_xor_sync(0xffffffffu, rm1, 2));

        const float mn0 = fmaxf(mx0, rm0);
        const float mn1 = fmaxf(mx1, rm1);
        const float corr0 = __expf(mx0 - mn0);
        const float corr1 = __expf(mx1 - mn1);
        mx0 = mn0; mx1 = mn1;

        float rs0 = 0.f, rs1 = 0.f;
#pragma unroll
        for (int j = 0; j < 8; j++) {
            sa[j][0] = __expf(sa[j][0] - mn0);
            sa[j][1] = __expf(sa[j][1] - mn0);
            sa[j][2] = __expf(sa[j][2] - mn1);
            sa[j][3] = __expf(sa[j][3] - mn1);
            rs0 += sa[j][0] + sa[j][1];
            rs1 += sa[j][2] + sa[j][3];
            oa[j][0] *= corr0; oa[j][1] *= corr0;
            oa[j][2] *= corr1; oa[j][3] *= corr1;
        }
        rs0 += __shfl_xor_sync(0xffffffffu, rs0, 1);
        rs0 += __shfl_xor_sync(0xffffffffu, rs0, 2);
        rs1 += __shfl_xor_sync(0xffffffffu, rs1, 1);
        rs1 += __shfl_xor_sync(0xffffffffu, rs1, 2);
        l0 = l0 * corr0 + rs0;
        l1 = l1 * corr1 + rs1;

        // ---- O += P @ V ----
#pragma unroll
        for (int ks = 0; ks < 4; ks++) {
            uint32_t pf[4];
            pf[0] = h2u(__floats2half2_rn(sa[2 * ks][0], sa[2 * ks][1]));
            pf[1] = h2u(__floats2half2_rn(sa[2 * ks][2], sa[2 * ks][3]));
            pf[2] = h2u(__floats2half2_rn(sa[2 * ks + 1][0], sa[2 * ks + 1][1]));
            pf[3] = h2u(__floats2half2_rn(sa[2 * ks + 1][2], sa[2 * ks + 1][3]));
#pragma unroll
            for (int q = 0; q < 4; q++) {
                uint32_t t4[4];
                ldsm_x4_t(t4, vc_u + (uint32_t)(((ks * 16 + lrow) * KROW + (2 * q + lhi) * 8) * 2));
                mma_f16(oa[2 * q], pf, t4);
                mma_f16(oa[2 * q + 1], pf, t4 + 2);
            }
        }
    }

    const float inv0 = 1.f / l0;
    const float inv1 = 1.f / l1;
    const int row0 = q0 + warp * 16 + r0;
    const size_t obase = (size_t)b * S_ * D_ + hoff;
#pragma unroll
    for (int j = 0; j < 8; j++) {
        const int col = j * 8 + 2 * c0;
        *(__half2*)(ctxh + obase + (size_t)row0 * D_ + col) =
            __floats2half2_rn(oa[j][0] * inv0, oa[j][1] * inv0);
        *(__half2*)(ctxh + obase + (size_t)(row0 + 8) * D_ + col) =
            __floats2half2_rn(oa[j][2] * inv1, oa[j][3] * inv1);
    }
}

// ---------------------------------------------------------------------------
// LayerNorm
// ---------------------------------------------------------------------------
__global__ __launch_bounds__(256) void ln_kernel(
    const float* __restrict__ in, const float* __restrict__ g,
    const float* __restrict__ be, float* __restrict__ out,
    __half* __restrict__ outh)
{
    __shared__ float sred[8], ssred[8];
    __shared__ float muSh, rsSh;

    const int row = blockIdx.x;
    const int tid = threadIdx.x;
    const int lane = tid & 31;
    const int wid = tid >> 5;

    const float* p = in + (size_t)row * D_;
    float4 x = *(const float4*)(p + tid * 4);
    float s = x.x + x.y + x.z + x.w;
    float ss = x.x * x.x + x.y * x.y + x.z * x.z + x.w * x.w;

#pragma unroll
    for (int off = 16; off > 0; off >>= 1) {
        s += __shfl_xor_sync(0xffffffffu, s, off);
        ss += __shfl_xor_sync(0xffffffffu, ss, off);
    }
    if (lane == 0) { sred[wid] = s; ssred[wid] = ss; }
    __syncthreads();
    if (wid == 0) {
        float s2 = (lane < 8) ? sred[lane] : 0.f;
        float ss2 = (lane < 8) ? ssred[lane] : 0.f;
#pragma unroll
        for (int off = 4; off > 0; off >>= 1) {
            s2 += __shfl_xor_sync(0xffffffffu, s2, off);
            ss2 += __shfl_xor_sync(0xffffffffu, ss2, off);
        }
        if (lane == 0) {
            const float mu = s2 * (1.f / D_);
            const float var = ss2 * (1.f / D_) - mu * mu;
            muSh = mu;
            rsSh = rsqrtf(var + 1e-6f);
        }
    }
    __syncthreads();

    const float mu = muSh, rs = rsSh;
    float4 gg = *(const float4*)(g + tid * 4);
    float4 bb = *(const float4*)(be + tid * 4);
    float4 y;
    y.x = (x.x - mu) * rs * gg.x + bb.x;
    y.y = (x.y - mu) * rs * gg.y + bb.y;
    y.z = (x.z - mu) * rs * gg.z + bb.z;
    y.w = (x.w - mu) * rs * gg.w + bb.w;
    *(float4*)(out + (size_t)row * D_ + tid * 4) = y;
    if (outh) {
        *(__half2*)(outh + (size_t)row * D_ + tid * 4)     = __floats2half2_rn(y.x, y.y);
        *(__half2*)(outh + (size_t)row * D_ + tid * 4 + 2) = __floats2half2_rn(y.z, y.w);
    }
}

// ---------------------------------------------------------------------------
// Launch
// ---------------------------------------------------------------------------
extern "C" void kernel_launch(void* const* d_in, const int* in_sizes, int n_in,
                              void* d_out, int out_size)
{
    const float* x   = (const float*)d_in[0];
    const unsigned char* mask = (const unsigned char*)d_in[1];
    const float* wq = (const float*)d_in[2];
    const float* bq = (const float*)d_in[3];
    const float* wk = (const float*)d_in[4];
    const float* bk = (const float*)d_in[5];
    const float* wv = (const float*)d_in[6];
    const float* bv = (const float*)d_in[7];
    const float* wm = (const float*)d_in[8];
    const float* bm = (const float*)d_in[9];
    const float* w1 = (const float*)d_in[10];
    const float* b1 = (const float*)d_in[11];
    const float* w2 = (const float*)d_in[12];
    const float* b2 = (const float*)d_in[13];
    const float* g1  = (const float*)d_in[14];
    const float* be1 = (const float*)d_in[15];
    const float* g2  = (const float*)d_in[16];
    const float* be2 = (const float*)d_in[17];
    float* out = (float*)d_out;

    float *y1, *x1, *bqkv, *mb;
    __half *xh, *whqkv, *wh, *qkvh, *ctxh, *x1h, *hbh;
    cudaGetSymbolAddress((void**)&y1, g_y1);
    cudaGetSymbolAddress((void**)&x1, g_x1);
    cudaGetSymbolAddress((void**)&bqkv, g_bqkv);
    cudaGetSymbolAddress((void**)&mb, g_mb);
    cudaGetSymbolAddress((void**)&xh, g_xh);
    cudaGetSymbolAddress((void**)&whqkv, g_whqkv);
    cudaGetSymbolAddress((void**)&wh, g_wh);
    cudaGetSymbolAddress((void**)&qkvh, g_qkvh);
    cudaGetSymbolAddress((void**)&ctxh, g_ctxh);
    cudaGetSymbolAddress((void**)&x1h, g_x1h);
    cudaGetSymbolAddress((void**)&hbh, g_hbh);

    __half* whm = wh;
    __half* wh1 = wh + (size_t)1 * 1024 * 1024;
    __half* wh2 = wh + (size_t)5 * 1024 * 1024;

    cudaFuncSetAttribute(hgemm_kernel<0, true>,  cudaFuncAttributeMaxDynamicSharedMemorySize, GEMM_SMEM_BYTES);
    cudaFuncSetAttribute(hgemm_kernel<1, true>,  cudaFuncAttributeMaxDynamicSharedMemorySize, GEMM_SMEM_BYTES);
    cudaFuncSetAttribute(hgemm_kernel<2, false>, cudaFuncAttributeMaxDynamicSharedMemorySize, GEMM_SMEM_BYTES);
    cudaFuncSetAttribute(flash_fp16_kernel, cudaFuncAttributeMaxDynamicSharedMemorySize, FLASH_SMEM_BYTES);

    static cudaStream_t s1 = nullptr;
    static cudaEvent_t ev_fork = nullptr, ev_join = nullptr;
    if (s1 == nullptr) {
        cudaStreamCreateWithFlags(&s1, cudaStreamNonBlocking);
        cudaEventCreateWithFlags(&ev_fork, cudaEventDisableTiming);
        cudaEventCreateWithFlags(&ev_join, cudaEventDisableTiming);
    }

    const dim3 blk(256);

    // Fused pre-pass (x convert + qkv weight pack + bias + mask bias)
    prep_main_kernel<<<11275, blk>>>(x, xh, wq, wk, wv, whqkv, bq, bk, bv, bqkv, mask, mb);

    // Fork: wm/w1/w2 conversion overlaps QKV GEMM + flash
    cudaEventRecord(ev_fork, 0);
    cudaStreamWaitEvent(s1, ev_fork, 0);
    prep_rest_kernel<<<9216, blk, 0, s1>>>(wm, w1, w2, whm, wh1, wh2);
    cudaEventRecord(ev_join, s1);

    // Packed QKV GEMM
    hgemm_kernel<0, true><<<dim3(QKS / 128, NTOK / 128), blk, GEMM_SMEM_BYTES>>>(
        xh, whqkv, bqkv, nullptr, qkvh, NTOK, QKS, D_);

    // Flash attention -> ctxh
    flash_fp16_kernel<<<dim3(S_ / 128, B_ * H_), blk, FLASH_SMEM_BYTES>>>(qkvh, mb, ctxh);

    // Join: converted wm/w1/w2 needed from here on
    cudaStreamWaitEvent(0, ev_join, 0);

    // proj + residual -> y1 (fp32)
    hgemm_kernel<2, false><<<dim3(D_ / 128, NTOK / 128), blk, GEMM_SMEM_BYTES>>>(
        ctxh, whm, bm, x, y1, NTOK, D_, D_);
    ln_kernel<<<NTOK, blk>>>(y1, g1, be1, x1, x1h);

    // FFN
    hgemm_kernel<1, true><<<dim3(FF_ / 128, NTOK / 128), blk, GEMM_SMEM_BYTES>>>(
        x1h, wh1, b1, nullptr, hbh, NTOK, FF_, D_);
    hgemm_kernel<2, false><<<dim3(D_ / 128, NTOK / 128), blk, GEMM_SMEM_BYTES>>>(
        hbh, wh2, b2, x1, y1, NTOK, D_, FF_);
    ln_kernel<<<NTOK, blk>>>(y1, g2, be2, out, nullptr);
}